// round 13
// baseline (speedup 1.0000x reference)
#include <cuda_runtime.h>
#include <math.h>
#include <stdint.h>

// ---------------------------------------------------------------------------
// Problem constants
// ---------------------------------------------------------------------------
#define BATCH   32
#define HRES    64
#define WRES    64
#define CDIM    256
#define WS      8
#define SHIFT   4
#define NH      8
#define NTOK    64
#define HD      32
#define HID     1024
#define CPB_HID 512
#define MROWS   (BATCH * HRES * WRES)   // 131072

// ---------------------------------------------------------------------------
// Scratch (allocation-free: __device__ globals)
// ---------------------------------------------------------------------------
__device__ float g_qkv[MROWS * 3 * CDIM];
__device__ float g_attnout[MROWS * CDIM];
__device__ float g_projimg[MROWS * CDIM];
__device__ float g_x1[MROWS * CDIM];
__device__ float g_h[MROWS * HID];
__device__ float g_mlp[MROWS * CDIM];
__device__ float g_bias_table[225 * NH];
__device__ float g_rpb[NH * NTOK * NTOK];

// ---------------------------------------------------------------------------
// shift+window permutation
// ---------------------------------------------------------------------------
__device__ __forceinline__ int permrow(int t) {
    int b   = t >> 12;
    int loc = t & 4095;
    int win = loc >> 6;
    int n   = loc & 63;
    int sh = ((win >> 3) << 3) + (n >> 3);
    int sw = ((win & 7) << 3) + (n & 7);
    int h = (sh + SHIFT) & 63;
    int w = (sw + SHIFT) & 63;
    return (b << 12) + (h << 6) + w;
}

// ---------------------------------------------------------------------------
// CPB table + rpb
// ---------------------------------------------------------------------------
__device__ __forceinline__ float cpb_feat(int v) {
    float tv = (float)v * (8.0f / 7.0f);
    float s  = (tv > 0.f) ? 1.f : ((tv < 0.f) ? -1.f : 0.f);
    return s * log2f(fabsf(tv) + 1.0f) * (1.0f / 3.0f);
}

__global__ __launch_bounds__(256)
void cpb_table_kernel(const float* __restrict__ w1, const float* __restrict__ b1,
                      const float* __restrict__ w2) {
    int p  = blockIdx.x;
    int iy = p / 15, ix = p % 15;
    float fy = cpb_feat(iy - 7);
    float fx = cpb_feat(ix - 7);
    int t = threadIdx.x;
    float acc[NH];
#pragma unroll
    for (int hh = 0; hh < NH; ++hh) acc[hh] = 0.f;
    for (int j = t; j < CPB_HID; j += 256) {
        float hmid = fy * w1[2 * j] + fx * w1[2 * j + 1] + b1[j];
        hmid = fmaxf(hmid, 0.f);
#pragma unroll
        for (int hh = 0; hh < NH; ++hh) acc[hh] += hmid * w2[hh * CPB_HID + j];
    }
    __shared__ float red[256];
    for (int hh = 0; hh < NH; ++hh) {
        red[t] = acc[hh];
        __syncthreads();
        for (int s = 128; s > 0; s >>= 1) {
            if (t < s) red[t] += red[t + s];
            __syncthreads();
        }
        if (t == 0) g_bias_table[p * NH + hh] = red[0];
        __syncthreads();
    }
}

__global__ __launch_bounds__(256)
void rpb_kernel() {
    int idx = blockIdx.x * 256 + threadIdx.x;
    if (idx >= NH * NTOK * NTOK) return;
    int h   = idx >> 12;
    int rem = idx & 4095;
    int i = rem >> 6, j = rem & 63;
    int ri = i >> 3, ci = i & 7, rj = j >> 3, cj = j & 7;
    int p = (ri - rj + 7) * 15 + (ci - cj + 7);
    float v = g_bias_table[p * NH + h];
    g_rpb[idx] = 16.0f / (1.0f + expf(-v));
}

// ---------------------------------------------------------------------------
// TF32 tensor-core GEMM with fragment-shuffled shared memory.
// 128x128 block, BK=16, 256 threads = 8 warps as 2(m) x 4(n); warp tile 64x32.
// Smem holds tiles already arranged per (warp, fragment, lane) so the
// consumer issues LDS.128 (A) / LDS.64 (B) instead of scalar gathers.
// ---------------------------------------------------------------------------
__device__ __forceinline__ uint32_t f2tf32(float f) {
    uint32_t r;
    asm("cvt.rna.tf32.f32 %0, %1;" : "=r"(r) : "f"(f));
    return r;
}

__device__ __forceinline__ void mma_tf32(float* c, const uint32_t* a, const uint32_t* b) {
    asm volatile(
        "mma.sync.aligned.m16n8k8.row.col.f32.tf32.tf32.f32 "
        "{%0,%1,%2,%3}, {%4,%5,%6,%7}, {%8,%9}, {%0,%1,%2,%3};"
        : "+f"(c[0]), "+f"(c[1]), "+f"(c[2]), "+f"(c[3])
        : "r"(a[0]), "r"(a[1]), "r"(a[2]), "r"(a[3]), "r"(b[0]), "r"(b[1]));
}

// A element (m in [0,128), k in [0,16)) -> slot in 2048-float fragment buffer
// region = ((m>>6)*4 + ((m>>4)&3))*2 + (k>>3); lane slot = (k&3)*8 + (m&7)
// idx = ((m>>3)&1) + 2*((k>>2)&1)
// B element (n in [0,128), k in [0,16)):
// region = ((n>>5)*4 + ((n>>3)&3))*2 + (k>>3); lane slot = (k&3)*8 + (n&7)
// idx = (k>>2)&1

__device__ __forceinline__ void stage_store_frag(
    float* Asb, float* Wsb, int abase0, int abase1, int bbase0, int bbase1,
    const float4& av0, const float4& av1, const float4& wv0, const float4& wv1) {
    Asb[abase0 +  0] = __uint_as_float(f2tf32(av0.x));
    Asb[abase0 + 32] = __uint_as_float(f2tf32(av0.y));
    Asb[abase0 + 64] = __uint_as_float(f2tf32(av0.z));
    Asb[abase0 + 96] = __uint_as_float(f2tf32(av0.w));
    Asb[abase1 +  0] = __uint_as_float(f2tf32(av1.x));
    Asb[abase1 + 32] = __uint_as_float(f2tf32(av1.y));
    Asb[abase1 + 64] = __uint_as_float(f2tf32(av1.z));
    Asb[abase1 + 96] = __uint_as_float(f2tf32(av1.w));
    Wsb[bbase0 +  0] = __uint_as_float(f2tf32(wv0.x));
    Wsb[bbase0 + 16] = __uint_as_float(f2tf32(wv0.y));
    Wsb[bbase0 + 32] = __uint_as_float(f2tf32(wv0.z));
    Wsb[bbase0 + 48] = __uint_as_float(f2tf32(wv0.w));
    Wsb[bbase1 +  0] = __uint_as_float(f2tf32(wv1.x));
    Wsb[bbase1 + 16] = __uint_as_float(f2tf32(wv1.y));
    Wsb[bbase1 + 32] = __uint_as_float(f2tf32(wv1.z));
    Wsb[bbase1 + 48] = __uint_as_float(f2tf32(wv1.w));
}

template <int RA, int RC, int BIASM, int ACT>
__global__ __launch_bounds__(256)
void tgemm_kernel(const float* __restrict__ A, const float* __restrict__ W,
                  const float* __restrict__ b0, const float* __restrict__ b1,
                  float* __restrict__ C, int M, int N, int K) {
    __shared__ float As[2][2048];
    __shared__ float Ws[2][2048];

    const int tid  = threadIdx.x;
    const int brow = blockIdx.y * 128;
    const int bcol = blockIdx.x * 128;

    // ---- global load mapping: rows lrow0 / lrow0+64, 4 consecutive k at lcol
    const int lrow0 = tid >> 2;            // 0..63
    const int lrow1 = lrow0 + 64;
    const int lcol  = (tid & 3) << 2;      // 0,4,8,12
    int ar0 = brow + lrow0, ar1 = brow + lrow1;
    if (RA) { ar0 = permrow(ar0); ar1 = permrow(ar1); }
    const float* A0 = A + (size_t)ar0 * K + lcol;
    const float* A1 = A + (size_t)ar1 * K + lcol;
    const float* W0 = W + (size_t)(bcol + lrow0) * K + lcol;
    const float* W1 = W + (size_t)(bcol + lrow1) * K + lcol;

    // ---- fragment-store bases (k varies by +1 -> +32 floats (A), +16 (B))
    const int ks_s = lcol >> 3;            // 0/1
    const int hi_s = (lcol >> 2) & 1;      // 0/1
    auto a_base = [&](int m) {
        int region = ((m >> 6) * 4 + ((m >> 4) & 3)) * 2 + ks_s;
        return region * 128 + (m & 7) * 4 + ((m >> 3) & 1) + 2 * hi_s;
    };
    auto b_base = [&](int n) {
        int region = ((n >> 5) * 4 + ((n >> 3) & 3)) * 2 + ks_s;
        return region * 64 + (n & 7) * 2 + hi_s;
    };
    const int ab0 = a_base(lrow0), ab1 = a_base(lrow1);
    const int bb0 = b_base(lrow0), bb1 = b_base(lrow1);

    // ---- warp tiling: 2(m) x 4(n), warp tile 64x32
    const int lane   = tid & 31;
    const int wid    = tid >> 5;
    const int warp_m = wid & 1;
    const int warp_n = wid >> 1;
    const int qr = lane >> 2;
    const int qc = lane & 3;
    const int slotA = ((lane & 3) * 8 + (lane >> 2)) * 4;   // consumer lane slot
    const int slotB = ((lane & 3) * 8 + (lane >> 2)) * 2;

    float acc[4][4][4];
#pragma unroll
    for (int mi = 0; mi < 4; ++mi)
#pragma unroll
        for (int ni = 0; ni < 4; ++ni)
#pragma unroll
            for (int e = 0; e < 4; ++e) acc[mi][ni][e] = 0.f;

    float4 av0 = *reinterpret_cast<const float4*>(A0);
    float4 av1 = *reinterpret_cast<const float4*>(A1);
    float4 wv0 = *reinterpret_cast<const float4*>(W0);
    float4 wv1 = *reinterpret_cast<const float4*>(W1);
    stage_store_frag(As[0], Ws[0], ab0, ab1, bb0, bb1, av0, av1, wv0, wv1);
    __syncthreads();

    const int nstages = K >> 4;
    for (int it = 0; it < nstages; ++it) {
        const int cur = it & 1;
        const int ktn = (it + 1) << 4;
        const bool more = ktn < K;
        if (more) {
            av0 = *reinterpret_cast<const float4*>(A0 + ktn);
            av1 = *reinterpret_cast<const float4*>(A1 + ktn);
            wv0 = *reinterpret_cast<const float4*>(W0 + ktn);
            wv1 = *reinterpret_cast<const float4*>(W1 + ktn);
        }
        const float* Ab = As[cur];
        const float* Wb = Ws[cur];
#pragma unroll
        for (int ks = 0; ks < 2; ++ks) {
            uint32_t afr[4][4];
#pragma unroll
            for (int mi = 0; mi < 4; ++mi) {
                float4 a4 = *reinterpret_cast<const float4*>(
                    Ab + ((warp_m * 4 + mi) * 2 + ks) * 128 + slotA);
                afr[mi][0] = __float_as_uint(a4.x);
                afr[mi][1] = __float_as_uint(a4.y);
                afr[mi][2] = __float_as_uint(a4.z);
                afr[mi][3] = __float_as_uint(a4.w);
            }
            uint32_t bfr[4][2];
#pragma unroll
            for (int ni = 0; ni < 4; ++ni) {
                float2 b2 = *reinterpret_cast<const float2*>(
                    Wb + ((warp_n * 4 + ni) * 2 + ks) * 64 + slotB);
                bfr[ni][0] = __float_as_uint(b2.x);
                bfr[ni][1] = __float_as_uint(b2.y);
            }
#pragma unroll
            for (int mi = 0; mi < 4; ++mi)
#pragma unroll
                for (int ni = 0; ni < 4; ++ni)
                    mma_tf32(acc[mi][ni], afr[mi], bfr[ni]);
        }
        if (more)
            stage_store_frag(As[cur ^ 1], Ws[cur ^ 1], ab0, ab1, bb0, bb1,
                             av0, av1, wv0, wv1);
        __syncthreads();
    }

    // ---- epilogue
#pragma unroll
    for (int mi = 0; mi < 4; ++mi) {
        int r0 = brow + warp_m * 64 + mi * 16 + qr;
        int r1 = r0 + 8;
        int cr0 = RC ? permrow(r0) : r0;
        int cr1 = RC ? permrow(r1) : r1;
        float* C0 = C + (size_t)cr0 * N;
        float* C1 = C + (size_t)cr1 * N;
#pragma unroll
        for (int ni = 0; ni < 4; ++ni) {
            int col = bcol + warp_n * 32 + ni * 8 + qc * 2;
            float bv0, bv1;
            if (BIASM == 0) {
                bv0 = b0[col]; bv1 = b0[col + 1];
            } else {
                bv0 = (col < 256) ? b0[col] : ((col < 512) ? 0.f : b1[col - 512]);
                int c1i = col + 1;
                bv1 = (c1i < 256) ? b0[c1i] : ((c1i < 512) ? 0.f : b1[c1i - 512]);
            }
            float v00 = acc[mi][ni][0] + bv0;
            float v01 = acc[mi][ni][1] + bv1;
            float v10 = acc[mi][ni][2] + bv0;
            float v11 = acc[mi][ni][3] + bv1;
            if (ACT == 1) {
                v00 = 0.5f * v00 * (1.0f + erff(v00 * 0.70710678118654752f));
                v01 = 0.5f * v01 * (1.0f + erff(v01 * 0.70710678118654752f));
                v10 = 0.5f * v10 * (1.0f + erff(v10 * 0.70710678118654752f));
                v11 = 0.5f * v11 * (1.0f + erff(v11 * 0.70710678118654752f));
            }
            *reinterpret_cast<float2*>(C0 + col) = make_float2(v00, v01);
            *reinterpret_cast<float2*>(C1 + col) = make_float2(v10, v11);
        }
    }
}

// ---------------------------------------------------------------------------
// Fused window attention
// ---------------------------------------------------------------------------
#define QS 36
#define PS 68

__global__ __launch_bounds__(256)
void attn_kernel(const float* __restrict__ qkv, const float* __restrict__ logit_scale,
                 float* __restrict__ out) {
    __shared__ float qs[NTOK * QS];
    __shared__ float ks[NTOK * QS];
    __shared__ float vs[NTOK * QS];
    __shared__ float ps[NTOK * PS];
    __shared__ int   grp[NTOK];

    const int blk = blockIdx.x;
    const int win = blk >> 3;
    const int h   = blk & 7;
    const int tid = threadIdx.x;
    const int t0  = win << 6;

    for (int e4 = tid; e4 < 1536; e4 += 256) {
        int tensor = e4 >> 9;
        int rem = e4 & 511;
        int n = rem >> 3;
        int hd4 = rem & 7;
        float4 val = *reinterpret_cast<const float4*>(
            qkv + (size_t)(t0 + n) * 768 + tensor * 256 + h * 32 + (hd4 << 2));
        float* dst = (tensor == 0 ? qs : (tensor == 1 ? ks : vs)) + n * QS + (hd4 << 2);
        *reinterpret_cast<float4*>(dst) = val;
    }
    if (tid < 64) {
        int wi = win & 63;
        int hh = ((wi >> 3) << 3) + (tid >> 3);
        int ww = ((wi & 7) << 3) + (tid & 7);
        int gh = (hh < 56) ? 0 : ((hh < 60) ? 1 : 2);
        int gw = (ww < 56) ? 0 : ((ww < 60) ? 1 : 2);
        grp[tid] = gh * 3 + gw;
    }
    __syncthreads();

    if (tid < 128) {
        float* base = (tid < 64 ? qs : ks) + (tid & 63) * QS;
        float4 r[8];
        float ss = 0.f;
#pragma unroll
        for (int d4 = 0; d4 < 8; ++d4) {
            r[d4] = *reinterpret_cast<const float4*>(base + (d4 << 2));
            ss += r[d4].x * r[d4].x + r[d4].y * r[d4].y
                + r[d4].z * r[d4].z + r[d4].w * r[d4].w;
        }
        float inv = 1.0f / fmaxf(sqrtf(ss), 1e-12f);
#pragma unroll
        for (int d4 = 0; d4 < 8; ++d4) {
            r[d4].x *= inv; r[d4].y *= inv; r[d4].z *= inv; r[d4].w *= inv;
            *reinterpret_cast<float4*>(base + (d4 << 2)) = r[d4];
        }
    }
    __syncthreads();

    const float scale = expf(fminf(logit_scale[h], 4.6051701859880914f));
    const int i  = tid >> 2;
    const int jq = tid & 3;
    const int wi = win & 63;
    const bool edge = ((wi >> 3) == 7) || ((wi & 7) == 7);

    float4 q4[8];
#pragma unroll
    for (int d4 = 0; d4 < 8; ++d4)
        q4[d4] = *reinterpret_cast<const float4*>(qs + i * QS + (d4 << 2));
    const int gi = grp[i];

    float lt[16];
#pragma unroll
    for (int jj = 0; jj < 16; ++jj) {
        const int j = (jj << 2) + jq;
        const float* kr = ks + j * QS;
        float dot = 0.f;
#pragma unroll
        for (int d4 = 0; d4 < 8; ++d4) {
            float4 k4 = *reinterpret_cast<const float4*>(kr + (d4 << 2));
            dot = fmaf(q4[d4].x, k4.x, dot);
            dot = fmaf(q4[d4].y, k4.y, dot);
            dot = fmaf(q4[d4].z, k4.z, dot);
            dot = fmaf(q4[d4].w, k4.w, dot);
        }
        float v = fmaf(scale, dot, g_rpb[h * 4096 + i * 64 + j]);
        if (edge && gi != grp[j]) v -= 100.0f;
        lt[jj] = v;
    }

    float m = lt[0];
#pragma unroll
    for (int jj = 1; jj < 16; ++jj) m = fmaxf(m, lt[jj]);
    m = fmaxf(m, __shfl_xor_sync(0xffffffffu, m, 1));
    m = fmaxf(m, __shfl_xor_sync(0xffffffffu, m, 2));
    float s = 0.f;
#pragma unroll
    for (int jj = 0; jj < 16; ++jj) { lt[jj] = __expf(lt[jj] - m); s += lt[jj]; }
    s += __shfl_xor_sync(0xffffffffu, s, 1);
    s += __shfl_xor_sync(0xffffffffu, s, 2);
    float inv = 1.0f / s;
#pragma unroll
    for (int jj = 0; jj < 16; ++jj)
        ps[i * PS + (jj << 2) + jq] = lt[jj] * inv;
    __syncthreads();

    {
        const int c0 = jq << 3;
        float acc[8];
#pragma unroll
        for (int e = 0; e < 8; ++e) acc[e] = 0.f;
        const float* pr = ps + i * PS;
#pragma unroll
        for (int j4 = 0; j4 < 16; ++j4) {
            float4 a4 = *reinterpret_cast<const float4*>(pr + (j4 << 2));
            float aj[4] = {a4.x, a4.y, a4.z, a4.w};
#pragma unroll
            for (int e = 0; e < 4; ++e) {
                const float* vb = vs + ((j4 << 2) + e) * QS + c0;
                float4 v0 = *reinterpret_cast<const float4*>(vb);
                float4 v1 = *reinterpret_cast<const float4*>(vb + 4);
                acc[0] = fmaf(aj[e], v0.x, acc[0]);
                acc[1] = fmaf(aj[e], v0.y, acc[1]);
                acc[2] = fmaf(aj[e], v0.z, acc[2]);
                acc[3] = fmaf(aj[e], v0.w, acc[3]);
                acc[4] = fmaf(aj[e], v1.x, acc[4]);
                acc[5] = fmaf(aj[e], v1.y, acc[5]);
                acc[6] = fmaf(aj[e], v1.z, acc[6]);
                acc[7] = fmaf(aj[e], v1.w, acc[7]);
            }
        }
        float* op = out + (size_t)(t0 + i) * 256 + h * 32 + c0;
        *reinterpret_cast<float4*>(op)     = make_float4(acc[0], acc[1], acc[2], acc[3]);
        *reinterpret_cast<float4*>(op + 4) = make_float4(acc[4], acc[5], acc[6], acc[7]);
    }
}

// ---------------------------------------------------------------------------
// out[row] = res[row] + LayerNorm(xin[row]) * g + b  — warp per row
// ---------------------------------------------------------------------------
__global__ __launch_bounds__(256)
void ln_add_kernel(const float* __restrict__ res, const float* __restrict__ xin,
                   const float* __restrict__ g, const float* __restrict__ b,
                   float* __restrict__ out) {
    const int row  = blockIdx.x * 8 + (threadIdx.x >> 5);
    const int lane = threadIdx.x & 31;
    const size_t base = (size_t)row * 256 + lane * 8;
    float4 v0 = *reinterpret_cast<const float4*>(xin + base);
    float4 v1 = *reinterpret_cast<const float4*>(xin + base + 4);
    float s = v0.x + v0.y + v0.z + v0.w + v1.x + v1.y + v1.z + v1.w;
#pragma unroll
    for (int o = 16; o > 0; o >>= 1) s += __shfl_xor_sync(0xffffffffu, s, o);
    float mean = s * (1.0f / 256.0f);
    float d0x = v0.x - mean, d0y = v0.y - mean, d0z = v0.z - mean, d0w = v0.w - mean;
    float d1x = v1.x - mean, d1y = v1.y - mean, d1z = v1.z - mean, d1w = v1.w - mean;
    float vv = d0x * d0x + d0y * d0y + d0z * d0z + d0w * d0w
             + d1x * d1x + d1y * d1y + d1z * d1z + d1w * d1w;
#pragma unroll
    for (int o = 16; o > 0; o >>= 1) vv += __shfl_xor_sync(0xffffffffu, vv, o);
    float rstd = rsqrtf(vv * (1.0f / 256.0f) + 1e-5f);
    float4 g0 = *reinterpret_cast<const float4*>(g + lane * 8);
    float4 g1 = *reinterpret_cast<const float4*>(g + lane * 8 + 4);
    float4 b0 = *reinterpret_cast<const float4*>(b + lane * 8);
    float4 b1 = *reinterpret_cast<const float4*>(b + lane * 8 + 4);
    float4 r0 = *reinterpret_cast<const float4*>(res + base);
    float4 r1 = *reinterpret_cast<const float4*>(res + base + 4);
    float4 o0, o1;
    o0.x = r0.x + d0x * rstd * g0.x + b0.x;
    o0.y = r0.y + d0y * rstd * g0.y + b0.y;
    o0.z = r0.z + d0z * rstd * g0.z + b0.z;
    o0.w = r0.w + d0w * rstd * g0.w + b0.w;
    o1.x = r1.x + d1x * rstd * g1.x + b1.x;
    o1.y = r1.y + d1y * rstd * g1.y + b1.y;
    o1.z = r1.z + d1z * rstd * g1.z + b1.z;
    o1.w = r1.w + d1w * rstd * g1.w + b1.w;
    *reinterpret_cast<float4*>(out + base)     = o0;
    *reinterpret_cast<float4*>(out + base + 4) = o1;
}

// ---------------------------------------------------------------------------
// launch
// ---------------------------------------------------------------------------
extern "C" void kernel_launch(void* const* d_in, const int* in_sizes, int n_in,
                              void* d_out, int out_size) {
    const float* x      = (const float*)d_in[0];
    const float* qkv_w  = (const float*)d_in[1];
    const float* q_bias = (const float*)d_in[2];
    const float* v_bias = (const float*)d_in[3];
    const float* lscale = (const float*)d_in[4];
    const float* cpb_w1 = (const float*)d_in[5];
    const float* cpb_b1 = (const float*)d_in[6];
    const float* cpb_w2 = (const float*)d_in[7];
    const float* proj_w = (const float*)d_in[8];
    const float* proj_b = (const float*)d_in[9];
    const float* n1g    = (const float*)d_in[10];
    const float* n1b    = (const float*)d_in[11];
    const float* n2g    = (const float*)d_in[12];
    const float* n2b    = (const float*)d_in[13];
    const float* fc1_w  = (const float*)d_in[14];
    const float* fc1_b  = (const float*)d_in[15];
    const float* fc2_w  = (const float*)d_in[16];
    const float* fc2_b  = (const float*)d_in[17];
    float* out = (float*)d_out;

    float *qkv, *attnout, *projimg, *x1, *hbuf, *mlp;
    cudaGetSymbolAddress((void**)&qkv,     g_qkv);
    cudaGetSymbolAddress((void**)&attnout, g_attnout);
    cudaGetSymbolAddress((void**)&projimg, g_projimg);
    cudaGetSymbolAddress((void**)&x1,      g_x1);
    cudaGetSymbolAddress((void**)&hbuf,    g_h);
    cudaGetSymbolAddress((void**)&mlp,     g_mlp);

    cpb_table_kernel<<<225, 256>>>(cpb_w1, cpb_b1, cpb_w2);
    rpb_kernel<<<(NH * NTOK * NTOK + 255) / 256, 256>>>();

    {   // QKV (gather shifted-window rows from x)
        dim3 grid(3 * CDIM / 128, MROWS / 128);
        tgemm_kernel<1, 0, 1, 0><<<grid, 256>>>(x, qkv_w, q_bias, v_bias, qkv,
                                                MROWS, 3 * CDIM, CDIM);
    }

    attn_kernel<<<(MROWS / NTOK) * NH, 256>>>(qkv, lscale, attnout);

    {   // proj (scatter rows back to image order)
        dim3 grid(CDIM / 128, MROWS / 128);
        tgemm_kernel<0, 1, 0, 0><<<grid, 256>>>(attnout, proj_w, proj_b, nullptr,
                                                projimg, MROWS, CDIM, CDIM);
    }

    ln_add_kernel<<<MROWS / 8, 256>>>(x, projimg, n1g, n1b, x1);

    {   // fc1 + exact GELU
        dim3 grid(HID / 128, MROWS / 128);
        tgemm_kernel<0, 0, 0, 1><<<grid, 256>>>(x1, fc1_w, fc1_b, nullptr, hbuf,
                                                MROWS, HID, CDIM);
    }

    {   // fc2
        dim3 grid(CDIM / 128, MROWS / 128);
        tgemm_kernel<0, 0, 0, 0><<<grid, 256>>>(hbuf, fc2_w, fc2_b, nullptr, mlp,
                                                MROWS, CDIM, HID);
    }

    ln_add_kernel<<<MROWS / 8, 256>>>(x1, mlp, n2g, n2b, out);
}

// round 14
// speedup vs baseline: 2.1306x; 2.1306x over previous
#include <cuda_runtime.h>
#include <math.h>
#include <stdint.h>

// ---------------------------------------------------------------------------
// Problem constants
// ---------------------------------------------------------------------------
#define BATCH   32
#define HRES    64
#define WRES    64
#define CDIM    256
#define WS      8
#define SHIFT   4
#define NH      8
#define NTOK    64
#define HD      32
#define HID     1024
#define CPB_HID 512
#define MROWS   (BATCH * HRES * WRES)   // 131072

// ---------------------------------------------------------------------------
// Scratch (allocation-free: __device__ globals)
// ---------------------------------------------------------------------------
__device__ float g_qkv[MROWS * 3 * CDIM];
__device__ float g_attnout[MROWS * CDIM];
__device__ float g_projimg[MROWS * CDIM];
__device__ float g_x1[MROWS * CDIM];
__device__ float g_h[MROWS * HID];
__device__ float g_mlp[MROWS * CDIM];
__device__ float g_bias_table[225 * NH];
__device__ float g_rpb[NH * NTOK * NTOK];

// ---------------------------------------------------------------------------
// shift+window permutation
// ---------------------------------------------------------------------------
__device__ __forceinline__ int permrow(int t) {
    int b   = t >> 12;
    int loc = t & 4095;
    int win = loc >> 6;
    int n   = loc & 63;
    int sh = ((win >> 3) << 3) + (n >> 3);
    int sw = ((win & 7) << 3) + (n & 7);
    int h = (sh + SHIFT) & 63;
    int w = (sw + SHIFT) & 63;
    return (b << 12) + (h << 6) + w;
}

// ---------------------------------------------------------------------------
// CPB table + rpb
// ---------------------------------------------------------------------------
__device__ __forceinline__ float cpb_feat(int v) {
    float tv = (float)v * (8.0f / 7.0f);
    float s  = (tv > 0.f) ? 1.f : ((tv < 0.f) ? -1.f : 0.f);
    return s * log2f(fabsf(tv) + 1.0f) * (1.0f / 3.0f);
}

__global__ __launch_bounds__(256)
void cpb_table_kernel(const float* __restrict__ w1, const float* __restrict__ b1,
                      const float* __restrict__ w2) {
    int p  = blockIdx.x;
    int iy = p / 15, ix = p % 15;
    float fy = cpb_feat(iy - 7);
    float fx = cpb_feat(ix - 7);
    int t = threadIdx.x;
    float acc[NH];
#pragma unroll
    for (int hh = 0; hh < NH; ++hh) acc[hh] = 0.f;
    for (int j = t; j < CPB_HID; j += 256) {
        float hmid = fy * w1[2 * j] + fx * w1[2 * j + 1] + b1[j];
        hmid = fmaxf(hmid, 0.f);
#pragma unroll
        for (int hh = 0; hh < NH; ++hh) acc[hh] += hmid * w2[hh * CPB_HID + j];
    }
    __shared__ float red[256];
    for (int hh = 0; hh < NH; ++hh) {
        red[t] = acc[hh];
        __syncthreads();
        for (int s = 128; s > 0; s >>= 1) {
            if (t < s) red[t] += red[t + s];
            __syncthreads();
        }
        if (t == 0) g_bias_table[p * NH + hh] = red[0];
        __syncthreads();
    }
}

__global__ __launch_bounds__(256)
void rpb_kernel() {
    int idx = blockIdx.x * 256 + threadIdx.x;
    if (idx >= NH * NTOK * NTOK) return;
    int h   = idx >> 12;
    int rem = idx & 4095;
    int i = rem >> 6, j = rem & 63;
    int ri = i >> 3, ci = i & 7, rj = j >> 3, cj = j & 7;
    int p = (ri - rj + 7) * 15 + (ci - cj + 7);
    float v = g_bias_table[p * NH + h];
    g_rpb[idx] = 16.0f / (1.0f + expf(-v));
}

// ---------------------------------------------------------------------------
// TF32 tensor-core GEMM, double-buffered smem (R8 proven configuration).
// 128x128 block tile, BK=16, 256 threads (8 warps, 4(m) x 2(n)), warp 32x64.
// ---------------------------------------------------------------------------
#define BKP 20

__device__ __forceinline__ uint32_t f2tf32(float f) {
    uint32_t r;
    asm("cvt.rna.tf32.f32 %0, %1;" : "=r"(r) : "f"(f));
    return r;
}

__device__ __forceinline__ void mma_tf32(float* c, const uint32_t* a, const uint32_t* b) {
    asm volatile(
        "mma.sync.aligned.m16n8k8.row.col.f32.tf32.tf32.f32 "
        "{%0,%1,%2,%3}, {%4,%5,%6,%7}, {%8,%9}, {%0,%1,%2,%3};"
        : "+f"(c[0]), "+f"(c[1]), "+f"(c[2]), "+f"(c[3])
        : "r"(a[0]), "r"(a[1]), "r"(a[2]), "r"(a[3]), "r"(b[0]), "r"(b[1]));
}

__device__ __forceinline__ void stage_store(float* Asb, float* Wsb,
                                            int lrow0, int lrow1, int lcol,
                                            const float4& av0, const float4& av1,
                                            const float4& wv0, const float4& wv1) {
    float* pa0 = Asb + lrow0 * BKP + lcol;
    float* pa1 = Asb + lrow1 * BKP + lcol;
    float* pw0 = Wsb + lrow0 * BKP + lcol;
    float* pw1 = Wsb + lrow1 * BKP + lcol;
    pa0[0] = __uint_as_float(f2tf32(av0.x)); pa0[1] = __uint_as_float(f2tf32(av0.y));
    pa0[2] = __uint_as_float(f2tf32(av0.z)); pa0[3] = __uint_as_float(f2tf32(av0.w));
    pa1[0] = __uint_as_float(f2tf32(av1.x)); pa1[1] = __uint_as_float(f2tf32(av1.y));
    pa1[2] = __uint_as_float(f2tf32(av1.z)); pa1[3] = __uint_as_float(f2tf32(av1.w));
    pw0[0] = __uint_as_float(f2tf32(wv0.x)); pw0[1] = __uint_as_float(f2tf32(wv0.y));
    pw0[2] = __uint_as_float(f2tf32(wv0.z)); pw0[3] = __uint_as_float(f2tf32(wv0.w));
    pw1[0] = __uint_as_float(f2tf32(wv1.x)); pw1[1] = __uint_as_float(f2tf32(wv1.y));
    pw1[2] = __uint_as_float(f2tf32(wv1.z)); pw1[3] = __uint_as_float(f2tf32(wv1.w));
}

template <int RA, int RC, int BIASM, int ACT>
__global__ __launch_bounds__(256)
void tgemm_kernel(const float* __restrict__ A, const float* __restrict__ W,
                  const float* __restrict__ b0, const float* __restrict__ b1,
                  float* __restrict__ C, int M, int N, int K) {
    __shared__ float As[2][128 * BKP];
    __shared__ float Ws[2][128 * BKP];

    const int tid  = threadIdx.x;
    const int brow = blockIdx.y * 128;
    const int bcol = blockIdx.x * 128;

    const int lrow0 = tid >> 2;
    const int lrow1 = lrow0 + 64;
    const int lcol  = (tid & 3) << 2;
    int ar0 = brow + lrow0, ar1 = brow + lrow1;
    if (RA) { ar0 = permrow(ar0); ar1 = permrow(ar1); }
    const float* A0 = A + (size_t)ar0 * K + lcol;
    const float* A1 = A + (size_t)ar1 * K + lcol;
    const float* W0 = W + (size_t)(bcol + lrow0) * K + lcol;
    const float* W1 = W + (size_t)(bcol + lrow1) * K + lcol;

    const int lane   = tid & 31;
    const int wid    = tid >> 5;
    const int warp_m = wid & 3;
    const int warp_n = wid >> 2;
    const int qr = lane >> 2;
    const int qc = lane & 3;
    const int aoff = (warp_m * 32 + qr) * BKP + qc;
    const int woff = (warp_n * 64 + qr) * BKP + qc;

    float acc[2][8][4];
#pragma unroll
    for (int mi = 0; mi < 2; ++mi)
#pragma unroll
        for (int ni = 0; ni < 8; ++ni)
#pragma unroll
            for (int e = 0; e < 4; ++e) acc[mi][ni][e] = 0.f;

    float4 av0 = *reinterpret_cast<const float4*>(A0);
    float4 av1 = *reinterpret_cast<const float4*>(A1);
    float4 wv0 = *reinterpret_cast<const float4*>(W0);
    float4 wv1 = *reinterpret_cast<const float4*>(W1);
    stage_store(As[0], Ws[0], lrow0, lrow1, lcol, av0, av1, wv0, wv1);
    __syncthreads();

    const int nstages = K >> 4;
    for (int it = 0; it < nstages; ++it) {
        const int cur = it & 1;
        const int ktn = (it + 1) << 4;
        const bool more = ktn < K;
        if (more) {
            av0 = *reinterpret_cast<const float4*>(A0 + ktn);
            av1 = *reinterpret_cast<const float4*>(A1 + ktn);
            wv0 = *reinterpret_cast<const float4*>(W0 + ktn);
            wv1 = *reinterpret_cast<const float4*>(W1 + ktn);
        }
        const float* Asm = As[cur] + aoff;
        const float* Wsm = Ws[cur] + woff;
#pragma unroll
        for (int ks = 0; ks < 2; ++ks) {
            const int kk = ks * 8;
            uint32_t afr[2][4];
#pragma unroll
            for (int mi = 0; mi < 2; ++mi) {
                const float* p = Asm + mi * 16 * BKP + kk;
                afr[mi][0] = __float_as_uint(p[0]);
                afr[mi][1] = __float_as_uint(p[8 * BKP]);
                afr[mi][2] = __float_as_uint(p[4]);
                afr[mi][3] = __float_as_uint(p[8 * BKP + 4]);
            }
            uint32_t bfr[8][2];
#pragma unroll
            for (int ni = 0; ni < 8; ++ni) {
                const float* p = Wsm + ni * 8 * BKP + kk;
                bfr[ni][0] = __float_as_uint(p[0]);
                bfr[ni][1] = __float_as_uint(p[4]);
            }
#pragma unroll
            for (int mi = 0; mi < 2; ++mi)
#pragma unroll
                for (int ni = 0; ni < 8; ++ni)
                    mma_tf32(acc[mi][ni], afr[mi], bfr[ni]);
        }
        if (more)
            stage_store(As[cur ^ 1], Ws[cur ^ 1], lrow0, lrow1, lcol, av0, av1, wv0, wv1);
        __syncthreads();
    }

    // ---- epilogue
#pragma unroll
    for (int mi = 0; mi < 2; ++mi) {
        int r0 = brow + warp_m * 32 + mi * 16 + qr;
        int r1 = r0 + 8;
        int cr0 = RC ? permrow(r0) : r0;
        int cr1 = RC ? permrow(r1) : r1;
        float* C0 = C + (size_t)cr0 * N;
        float* C1 = C + (size_t)cr1 * N;
#pragma unroll
        for (int ni = 0; ni < 8; ++ni) {
            int col = bcol + warp_n * 64 + ni * 8 + qc * 2;
            float bv0, bv1;
            if (BIASM == 0) {
                bv0 = b0[col]; bv1 = b0[col + 1];
            } else {
                bv0 = (col < 256) ? b0[col] : ((col < 512) ? 0.f : b1[col - 512]);
                int c1i = col + 1;
                bv1 = (c1i < 256) ? b0[c1i] : ((c1i < 512) ? 0.f : b1[c1i - 512]);
            }
            float v00 = acc[mi][ni][0] + bv0;
            float v01 = acc[mi][ni][1] + bv1;
            float v10 = acc[mi][ni][2] + bv0;
            float v11 = acc[mi][ni][3] + bv1;
            if (ACT == 1) {
                v00 = 0.5f * v00 * (1.0f + erff(v00 * 0.70710678118654752f));
                v01 = 0.5f * v01 * (1.0f + erff(v01 * 0.70710678118654752f));
                v10 = 0.5f * v10 * (1.0f + erff(v10 * 0.70710678118654752f));
                v11 = 0.5f * v11 * (1.0f + erff(v11 * 0.70710678118654752f));
            }
            *reinterpret_cast<float2*>(C0 + col) = make_float2(v00, v01);
            *reinterpret_cast<float2*>(C1 + col) = make_float2(v10, v11);
        }
    }
}

// ---------------------------------------------------------------------------
// Fused window attention (R8 proven version)
// ---------------------------------------------------------------------------
#define QS 36
#define PS 68

__global__ __launch_bounds__(256)
void attn_kernel(const float* __restrict__ qkv, const float* __restrict__ logit_scale,
                 float* __restrict__ out) {
    __shared__ float qs[NTOK * QS];
    __shared__ float ks[NTOK * QS];
    __shared__ float vs[NTOK * QS];
    __shared__ float ps[NTOK * PS];
    __shared__ int   grp[NTOK];

    const int blk = blockIdx.x;
    const int win = blk >> 3;
    const int h   = blk & 7;
    const int tid = threadIdx.x;
    const int t0  = win << 6;

    for (int e4 = tid; e4 < 1536; e4 += 256) {
        int tensor = e4 >> 9;
        int rem = e4 & 511;
        int n = rem >> 3;
        int hd4 = rem & 7;
        float4 val = *reinterpret_cast<const float4*>(
            qkv + (size_t)(t0 + n) * 768 + tensor * 256 + h * 32 + (hd4 << 2));
        float* dst = (tensor == 0 ? qs : (tensor == 1 ? ks : vs)) + n * QS + (hd4 << 2);
        *reinterpret_cast<float4*>(dst) = val;
    }
    if (tid < 64) {
        int wi = win & 63;
        int hh = ((wi >> 3) << 3) + (tid >> 3);
        int ww = ((wi & 7) << 3) + (tid & 7);
        int gh = (hh < 56) ? 0 : ((hh < 60) ? 1 : 2);
        int gw = (ww < 56) ? 0 : ((ww < 60) ? 1 : 2);
        grp[tid] = gh * 3 + gw;
    }
    __syncthreads();

    if (tid < 128) {
        float* base = (tid < 64 ? qs : ks) + (tid & 63) * QS;
        float4 r[8];
        float ss = 0.f;
#pragma unroll
        for (int d4 = 0; d4 < 8; ++d4) {
            r[d4] = *reinterpret_cast<const float4*>(base + (d4 << 2));
            ss += r[d4].x * r[d4].x + r[d4].y * r[d4].y
                + r[d4].z * r[d4].z + r[d4].w * r[d4].w;
        }
        float inv = 1.0f / fmaxf(sqrtf(ss), 1e-12f);
#pragma unroll
        for (int d4 = 0; d4 < 8; ++d4) {
            r[d4].x *= inv; r[d4].y *= inv; r[d4].z *= inv; r[d4].w *= inv;
            *reinterpret_cast<float4*>(base + (d4 << 2)) = r[d4];
        }
    }
    __syncthreads();

    const float scale = expf(fminf(logit_scale[h], 4.6051701859880914f));
    const int i  = tid >> 2;
    const int jq = tid & 3;
    const int wi = win & 63;
    const bool edge = ((wi >> 3) == 7) || ((wi & 7) == 7);

    float4 q4[8];
#pragma unroll
    for (int d4 = 0; d4 < 8; ++d4)
        q4[d4] = *reinterpret_cast<const float4*>(qs + i * QS + (d4 << 2));
    const int gi = grp[i];

    float lt[16];
#pragma unroll
    for (int jj = 0; jj < 16; ++jj) {
        const int j = (jj << 2) + jq;
        const float* kr = ks + j * QS;
        float dot = 0.f;
#pragma unroll
        for (int d4 = 0; d4 < 8; ++d4) {
            float4 k4 = *reinterpret_cast<const float4*>(kr + (d4 << 2));
            dot = fmaf(q4[d4].x, k4.x, dot);
            dot = fmaf(q4[d4].y, k4.y, dot);
            dot = fmaf(q4[d4].z, k4.z, dot);
            dot = fmaf(q4[d4].w, k4.w, dot);
        }
        float v = fmaf(scale, dot, g_rpb[h * 4096 + i * 64 + j]);
        if (edge && gi != grp[j]) v -= 100.0f;
        lt[jj] = v;
    }

    float m = lt[0];
#pragma unroll
    for (int jj = 1; jj < 16; ++jj) m = fmaxf(m, lt[jj]);
    m = fmaxf(m, __shfl_xor_sync(0xffffffffu, m, 1));
    m = fmaxf(m, __shfl_xor_sync(0xffffffffu, m, 2));
    float s = 0.f;
#pragma unroll
    for (int jj = 0; jj < 16; ++jj) { lt[jj] = __expf(lt[jj] - m); s += lt[jj]; }
    s += __shfl_xor_sync(0xffffffffu, s, 1);
    s += __shfl_xor_sync(0xffffffffu, s, 2);
    float inv = 1.0f / s;
#pragma unroll
    for (int jj = 0; jj < 16; ++jj)
        ps[i * PS + (jj << 2) + jq] = lt[jj] * inv;
    __syncthreads();

    {
        const int c0 = jq << 3;
        float acc[8];
#pragma unroll
        for (int e = 0; e < 8; ++e) acc[e] = 0.f;
        const float* pr = ps + i * PS;
#pragma unroll
        for (int j4 = 0; j4 < 16; ++j4) {
            float4 a4 = *reinterpret_cast<const float4*>(pr + (j4 << 2));
            float aj[4] = {a4.x, a4.y, a4.z, a4.w};
#pragma unroll
            for (int e = 0; e < 4; ++e) {
                const float* vb = vs + ((j4 << 2) + e) * QS + c0;
                float4 v0 = *reinterpret_cast<const float4*>(vb);
                float4 v1 = *reinterpret_cast<const float4*>(vb + 4);
                acc[0] = fmaf(aj[e], v0.x, acc[0]);
                acc[1] = fmaf(aj[e], v0.y, acc[1]);
                acc[2] = fmaf(aj[e], v0.z, acc[2]);
                acc[3] = fmaf(aj[e], v0.w, acc[3]);
                acc[4] = fmaf(aj[e], v1.x, acc[4]);
                acc[5] = fmaf(aj[e], v1.y, acc[5]);
                acc[6] = fmaf(aj[e], v1.z, acc[6]);
                acc[7] = fmaf(aj[e], v1.w, acc[7]);
            }
        }
        float* op = out + (size_t)(t0 + i) * 256 + h * 32 + c0;
        *reinterpret_cast<float4*>(op)     = make_float4(acc[0], acc[1], acc[2], acc[3]);
        *reinterpret_cast<float4*>(op + 4) = make_float4(acc[4], acc[5], acc[6], acc[7]);
    }
}

// ---------------------------------------------------------------------------
// out[row] = res[row] + LayerNorm(xin[row]) * g + b  — warp per row
// ---------------------------------------------------------------------------
__global__ __launch_bounds__(256)
void ln_add_kernel(const float* __restrict__ res, const float* __restrict__ xin,
                   const float* __restrict__ g, const float* __restrict__ b,
                   float* __restrict__ out) {
    const int row  = blockIdx.x * 8 + (threadIdx.x >> 5);
    const int lane = threadIdx.x & 31;
    const size_t base = (size_t)row * 256 + lane * 8;
    float4 v0 = *reinterpret_cast<const float4*>(xin + base);
    float4 v1 = *reinterpret_cast<const float4*>(xin + base + 4);
    float s = v0.x + v0.y + v0.z + v0.w + v1.x + v1.y + v1.z + v1.w;
#pragma unroll
    for (int o = 16; o > 0; o >>= 1) s += __shfl_xor_sync(0xffffffffu, s, o);
    float mean = s * (1.0f / 256.0f);
    float d0x = v0.x - mean, d0y = v0.y - mean, d0z = v0.z - mean, d0w = v0.w - mean;
    float d1x = v1.x - mean, d1y = v1.y - mean, d1z = v1.z - mean, d1w = v1.w - mean;
    float vv = d0x * d0x + d0y * d0y + d0z * d0z + d0w * d0w
             + d1x * d1x + d1y * d1y + d1z * d1z + d1w * d1w;
#pragma unroll
    for (int o = 16; o > 0; o >>= 1) vv += __shfl_xor_sync(0xffffffffu, vv, o);
    float rstd = rsqrtf(vv * (1.0f / 256.0f) + 1e-5f);
    float4 g0 = *reinterpret_cast<const float4*>(g + lane * 8);
    float4 g1 = *reinterpret_cast<const float4*>(g + lane * 8 + 4);
    float4 b0 = *reinterpret_cast<const float4*>(b + lane * 8);
    float4 b1 = *reinterpret_cast<const float4*>(b + lane * 8 + 4);
    float4 r0 = *reinterpret_cast<const float4*>(res + base);
    float4 r1 = *reinterpret_cast<const float4*>(res + base + 4);
    float4 o0, o1;
    o0.x = r0.x + d0x * rstd * g0.x + b0.x;
    o0.y = r0.y + d0y * rstd * g0.y + b0.y;
    o0.z = r0.z + d0z * rstd * g0.z + b0.z;
    o0.w = r0.w + d0w * rstd * g0.w + b0.w;
    o1.x = r1.x + d1x * rstd * g1.x + b1.x;
    o1.y = r1.y + d1y * rstd * g1.y + b1.y;
    o1.z = r1.z + d1z * rstd * g1.z + b1.z;
    o1.w = r1.w + d1w * rstd * g1.w + b1.w;
    *reinterpret_cast<float4*>(out + base)     = o0;
    *reinterpret_cast<float4*>(out + base + 4) = o1;
}

// ---------------------------------------------------------------------------
// launch
// ---------------------------------------------------------------------------
extern "C" void kernel_launch(void* const* d_in, const int* in_sizes, int n_in,
                              void* d_out, int out_size) {
    const float* x      = (const float*)d_in[0];
    const float* qkv_w  = (const float*)d_in[1];
    const float* q_bias = (const float*)d_in[2];
    const float* v_bias = (const float*)d_in[3];
    const float* lscale = (const float*)d_in[4];
    const float* cpb_w1 = (const float*)d_in[5];
    const float* cpb_b1 = (const float*)d_in[6];
    const float* cpb_w2 = (const float*)d_in[7];
    const float* proj_w = (const float*)d_in[8];
    const float* proj_b = (const float*)d_in[9];
    const float* n1g    = (const float*)d_in[10];
    const float* n1b    = (const float*)d_in[11];
    const float* n2g    = (const float*)d_in[12];
    const float* n2b    = (const float*)d_in[13];
    const float* fc1_w  = (const float*)d_in[14];
    const float* fc1_b  = (const float*)d_in[15];
    const float* fc2_w  = (const float*)d_in[16];
    const float* fc2_b  = (const float*)d_in[17];
    float* out = (float*)d_out;

    float *qkv, *attnout, *projimg, *x1, *hbuf, *mlp;
    cudaGetSymbolAddress((void**)&qkv,     g_qkv);
    cudaGetSymbolAddress((void**)&attnout, g_attnout);
    cudaGetSymbolAddress((void**)&projimg, g_projimg);
    cudaGetSymbolAddress((void**)&x1,      g_x1);
    cudaGetSymbolAddress((void**)&hbuf,    g_h);
    cudaGetSymbolAddress((void**)&mlp,     g_mlp);

    cpb_table_kernel<<<225, 256>>>(cpb_w1, cpb_b1, cpb_w2);
    rpb_kernel<<<(NH * NTOK * NTOK + 255) / 256, 256>>>();

    {   // QKV (gather shifted-window rows from x)
        dim3 grid(3 * CDIM / 128, MROWS / 128);
        tgemm_kernel<1, 0, 1, 0><<<grid, 256>>>(x, qkv_w, q_bias, v_bias, qkv,
                                                MROWS, 3 * CDIM, CDIM);
    }

    attn_kernel<<<(MROWS / NTOK) * NH, 256>>>(qkv, lscale, attnout);

    {   // proj (scatter rows back to image order)
        dim3 grid(CDIM / 128, MROWS / 128);
        tgemm_kernel<0, 1, 0, 0><<<grid, 256>>>(attnout, proj_w, proj_b, nullptr,
                                                projimg, MROWS, CDIM, CDIM);
    }

    ln_add_kernel<<<MROWS / 8, 256>>>(x, projimg, n1g, n1b, x1);

    {   // fc1 + exact GELU
        dim3 grid(HID / 128, MROWS / 128);
        tgemm_kernel<0, 0, 0, 1><<<grid, 256>>>(x1, fc1_w, fc1_b, nullptr, hbuf,
                                                MROWS, HID, CDIM);
    }

    {   // fc2
        dim3 grid(CDIM / 128, MROWS / 128);
        tgemm_kernel<0, 0, 0, 0><<<grid, 256>>>(hbuf, fc2_w, fc2_b, nullptr, mlp,
                                                MROWS, CDIM, HID);
    }

    ln_add_kernel<<<MROWS / 8, 256>>>(x1, mlp, n2g, n2b, out);
}

// round 15
// speedup vs baseline: 2.2082x; 1.0364x over previous
#include <cuda_runtime.h>
#include <math.h>
#include <stdint.h>

// ---------------------------------------------------------------------------
// Problem constants
// ---------------------------------------------------------------------------
#define BATCH   32
#define HRES    64
#define WRES    64
#define CDIM    256
#define WS      8
#define SHIFT   4
#define NH      8
#define NTOK    64
#define HD      32
#define HID     1024
#define CPB_HID 512
#define MROWS   (BATCH * HRES * WRES)   // 131072

// ---------------------------------------------------------------------------
// Scratch (allocation-free: __device__ globals)
// ---------------------------------------------------------------------------
__device__ float g_qkv[MROWS * 3 * CDIM];
__device__ float g_attnout[MROWS * CDIM];
__device__ float g_projimg[MROWS * CDIM];
__device__ float g_x1[MROWS * CDIM];
__device__ float g_h[MROWS * HID];
__device__ float g_mlp[MROWS * CDIM];
__device__ float g_bias_table[225 * NH];
__device__ float g_rpb[NH * NTOK * NTOK];

// ---------------------------------------------------------------------------
// shift+window permutation
// ---------------------------------------------------------------------------
__device__ __forceinline__ int permrow(int t) {
    int b   = t >> 12;
    int loc = t & 4095;
    int win = loc >> 6;
    int n   = loc & 63;
    int sh = ((win >> 3) << 3) + (n >> 3);
    int sw = ((win & 7) << 3) + (n & 7);
    int h = (sh + SHIFT) & 63;
    int w = (sw + SHIFT) & 63;
    return (b << 12) + (h << 6) + w;
}

// ---------------------------------------------------------------------------
// CPB table + rpb
// ---------------------------------------------------------------------------
__device__ __forceinline__ float cpb_feat(int v) {
    float tv = (float)v * (8.0f / 7.0f);
    float s  = (tv > 0.f) ? 1.f : ((tv < 0.f) ? -1.f : 0.f);
    return s * log2f(fabsf(tv) + 1.0f) * (1.0f / 3.0f);
}

__global__ __launch_bounds__(256)
void cpb_table_kernel(const float* __restrict__ w1, const float* __restrict__ b1,
                      const float* __restrict__ w2) {
    int p  = blockIdx.x;
    int iy = p / 15, ix = p % 15;
    float fy = cpb_feat(iy - 7);
    float fx = cpb_feat(ix - 7);
    int t = threadIdx.x;
    float acc[NH];
#pragma unroll
    for (int hh = 0; hh < NH; ++hh) acc[hh] = 0.f;
    for (int j = t; j < CPB_HID; j += 256) {
        float hmid = fy * w1[2 * j] + fx * w1[2 * j + 1] + b1[j];
        hmid = fmaxf(hmid, 0.f);
#pragma unroll
        for (int hh = 0; hh < NH; ++hh) acc[hh] += hmid * w2[hh * CPB_HID + j];
    }
    __shared__ float red[256];
    for (int hh = 0; hh < NH; ++hh) {
        red[t] = acc[hh];
        __syncthreads();
        for (int s = 128; s > 0; s >>= 1) {
            if (t < s) red[t] += red[t + s];
            __syncthreads();
        }
        if (t == 0) g_bias_table[p * NH + hh] = red[0];
        __syncthreads();
    }
}

__global__ __launch_bounds__(256)
void rpb_kernel() {
    int idx = blockIdx.x * 256 + threadIdx.x;
    if (idx >= NH * NTOK * NTOK) return;
    int h   = idx >> 12;
    int rem = idx & 4095;
    int i = rem >> 6, j = rem & 63;
    int ri = i >> 3, ci = i & 7, rj = j >> 3, cj = j & 7;
    int p = (ri - rj + 7) * 15 + (ci - cj + 7);
    float v = g_bias_table[p * NH + h];
    g_rpb[idx] = 16.0f / (1.0f + expf(-v));
}

// ---------------------------------------------------------------------------
// TF32 tensor-core GEMM, double-buffered smem (R14 proven configuration).
// ---------------------------------------------------------------------------
#define BKP 20

__device__ __forceinline__ uint32_t f2tf32(float f) {
    uint32_t r;
    asm("cvt.rna.tf32.f32 %0, %1;" : "=r"(r) : "f"(f));
    return r;
}

__device__ __forceinline__ void mma_tf32(float* c, const uint32_t* a, const uint32_t* b) {
    asm volatile(
        "mma.sync.aligned.m16n8k8.row.col.f32.tf32.tf32.f32 "
        "{%0,%1,%2,%3}, {%4,%5,%6,%7}, {%8,%9}, {%0,%1,%2,%3};"
        : "+f"(c[0]), "+f"(c[1]), "+f"(c[2]), "+f"(c[3])
        : "r"(a[0]), "r"(a[1]), "r"(a[2]), "r"(a[3]), "r"(b[0]), "r"(b[1]));
}

__device__ __forceinline__ void stage_store(float* Asb, float* Wsb,
                                            int lrow0, int lrow1, int lcol,
                                            const float4& av0, const float4& av1,
                                            const float4& wv0, const float4& wv1) {
    float* pa0 = Asb + lrow0 * BKP + lcol;
    float* pa1 = Asb + lrow1 * BKP + lcol;
    float* pw0 = Wsb + lrow0 * BKP + lcol;
    float* pw1 = Wsb + lrow1 * BKP + lcol;
    pa0[0] = __uint_as_float(f2tf32(av0.x)); pa0[1] = __uint_as_float(f2tf32(av0.y));
    pa0[2] = __uint_as_float(f2tf32(av0.z)); pa0[3] = __uint_as_float(f2tf32(av0.w));
    pa1[0] = __uint_as_float(f2tf32(av1.x)); pa1[1] = __uint_as_float(f2tf32(av1.y));
    pa1[2] = __uint_as_float(f2tf32(av1.z)); pa1[3] = __uint_as_float(f2tf32(av1.w));
    pw0[0] = __uint_as_float(f2tf32(wv0.x)); pw0[1] = __uint_as_float(f2tf32(wv0.y));
    pw0[2] = __uint_as_float(f2tf32(wv0.z)); pw0[3] = __uint_as_float(f2tf32(wv0.w));
    pw1[0] = __uint_as_float(f2tf32(wv1.x)); pw1[1] = __uint_as_float(f2tf32(wv1.y));
    pw1[2] = __uint_as_float(f2tf32(wv1.z)); pw1[3] = __uint_as_float(f2tf32(wv1.w));
}

template <int RA, int RC, int BIASM, int ACT>
__global__ __launch_bounds__(256)
void tgemm_kernel(const float* __restrict__ A, const float* __restrict__ W,
                  const float* __restrict__ b0, const float* __restrict__ b1,
                  float* __restrict__ C, int M, int N, int K) {
    __shared__ float As[2][128 * BKP];
    __shared__ float Ws[2][128 * BKP];

    const int tid  = threadIdx.x;
    const int brow = blockIdx.y * 128;
    const int bcol = blockIdx.x * 128;

    const int lrow0 = tid >> 2;
    const int lrow1 = lrow0 + 64;
    const int lcol  = (tid & 3) << 2;
    int ar0 = brow + lrow0, ar1 = brow + lrow1;
    if (RA) { ar0 = permrow(ar0); ar1 = permrow(ar1); }
    const float* A0 = A + (size_t)ar0 * K + lcol;
    const float* A1 = A + (size_t)ar1 * K + lcol;
    const float* W0 = W + (size_t)(bcol + lrow0) * K + lcol;
    const float* W1 = W + (size_t)(bcol + lrow1) * K + lcol;

    const int lane   = tid & 31;
    const int wid    = tid >> 5;
    const int warp_m = wid & 3;
    const int warp_n = wid >> 2;
    const int qr = lane >> 2;
    const int qc = lane & 3;
    const int aoff = (warp_m * 32 + qr) * BKP + qc;
    const int woff = (warp_n * 64 + qr) * BKP + qc;

    float acc[2][8][4];
#pragma unroll
    for (int mi = 0; mi < 2; ++mi)
#pragma unroll
        for (int ni = 0; ni < 8; ++ni)
#pragma unroll
            for (int e = 0; e < 4; ++e) acc[mi][ni][e] = 0.f;

    float4 av0 = *reinterpret_cast<const float4*>(A0);
    float4 av1 = *reinterpret_cast<const float4*>(A1);
    float4 wv0 = *reinterpret_cast<const float4*>(W0);
    float4 wv1 = *reinterpret_cast<const float4*>(W1);
    stage_store(As[0], Ws[0], lrow0, lrow1, lcol, av0, av1, wv0, wv1);
    __syncthreads();

    const int nstages = K >> 4;
    for (int it = 0; it < nstages; ++it) {
        const int cur = it & 1;
        const int ktn = (it + 1) << 4;
        const bool more = ktn < K;
        if (more) {
            av0 = *reinterpret_cast<const float4*>(A0 + ktn);
            av1 = *reinterpret_cast<const float4*>(A1 + ktn);
            wv0 = *reinterpret_cast<const float4*>(W0 + ktn);
            wv1 = *reinterpret_cast<const float4*>(W1 + ktn);
        }
        const float* Asm = As[cur] + aoff;
        const float* Wsm = Ws[cur] + woff;
#pragma unroll
        for (int ks = 0; ks < 2; ++ks) {
            const int kk = ks * 8;
            uint32_t afr[2][4];
#pragma unroll
            for (int mi = 0; mi < 2; ++mi) {
                const float* p = Asm + mi * 16 * BKP + kk;
                afr[mi][0] = __float_as_uint(p[0]);
                afr[mi][1] = __float_as_uint(p[8 * BKP]);
                afr[mi][2] = __float_as_uint(p[4]);
                afr[mi][3] = __float_as_uint(p[8 * BKP + 4]);
            }
            uint32_t bfr[8][2];
#pragma unroll
            for (int ni = 0; ni < 8; ++ni) {
                const float* p = Wsm + ni * 8 * BKP + kk;
                bfr[ni][0] = __float_as_uint(p[0]);
                bfr[ni][1] = __float_as_uint(p[4]);
            }
#pragma unroll
            for (int mi = 0; mi < 2; ++mi)
#pragma unroll
                for (int ni = 0; ni < 8; ++ni)
                    mma_tf32(acc[mi][ni], afr[mi], bfr[ni]);
        }
        if (more)
            stage_store(As[cur ^ 1], Ws[cur ^ 1], lrow0, lrow1, lcol, av0, av1, wv0, wv1);
        __syncthreads();
    }

    // ---- epilogue
#pragma unroll
    for (int mi = 0; mi < 2; ++mi) {
        int r0 = brow + warp_m * 32 + mi * 16 + qr;
        int r1 = r0 + 8;
        int cr0 = RC ? permrow(r0) : r0;
        int cr1 = RC ? permrow(r1) : r1;
        float* C0 = C + (size_t)cr0 * N;
        float* C1 = C + (size_t)cr1 * N;
#pragma unroll
        for (int ni = 0; ni < 8; ++ni) {
            int col = bcol + warp_n * 64 + ni * 8 + qc * 2;
            float bv0, bv1;
            if (BIASM == 0) {
                bv0 = b0[col]; bv1 = b0[col + 1];
            } else {
                bv0 = (col < 256) ? b0[col] : ((col < 512) ? 0.f : b1[col - 512]);
                int c1i = col + 1;
                bv1 = (c1i < 256) ? b0[c1i] : ((c1i < 512) ? 0.f : b1[c1i - 512]);
            }
            float v00 = acc[mi][ni][0] + bv0;
            float v01 = acc[mi][ni][1] + bv1;
            float v10 = acc[mi][ni][2] + bv0;
            float v11 = acc[mi][ni][3] + bv1;
            if (ACT == 1) {
                v00 = 0.5f * v00 * (1.0f + erff(v00 * 0.70710678118654752f));
                v01 = 0.5f * v01 * (1.0f + erff(v01 * 0.70710678118654752f));
                v10 = 0.5f * v10 * (1.0f + erff(v10 * 0.70710678118654752f));
                v11 = 0.5f * v11 * (1.0f + erff(v11 * 0.70710678118654752f));
            }
            *reinterpret_cast<float2*>(C0 + col) = make_float2(v00, v01);
            *reinterpret_cast<float2*>(C1 + col) = make_float2(v10, v11);
        }
    }
}

// ---------------------------------------------------------------------------
// Fused window attention: 2 rows per thread to halve smem traffic.
// Logits: 128 threads, thread (ip, jq) does rows {2ip, 2ip+1} x 16 cols
//   (j = 4*jj + jq) — K-row load pattern identical to proven R8 (conflict-free).
// AV: 256 threads, thread (ip2, cg) does rows {2*ip2, 2*ip2+1} x 4 cols.
// Identical FLOP order -> bitwise-identical results to R14.
// ---------------------------------------------------------------------------
#define QS 36
#define PS 68

__global__ __launch_bounds__(256)
void attn_kernel(const float* __restrict__ qkv, const float* __restrict__ logit_scale,
                 float* __restrict__ out) {
    __shared__ float qs[NTOK * QS];
    __shared__ float ks[NTOK * QS];
    __shared__ float vs[NTOK * QS];
    __shared__ float ps[NTOK * PS];
    __shared__ int   grp[NTOK];

    const int blk = blockIdx.x;
    const int win = blk >> 3;
    const int h   = blk & 7;
    const int tid = threadIdx.x;
    const int t0  = win << 6;

    // load q/k/v head slices (1536 float4)
    for (int e4 = tid; e4 < 1536; e4 += 256) {
        int tensor = e4 >> 9;
        int rem = e4 & 511;
        int n = rem >> 3;
        int hd4 = rem & 7;
        float4 val = *reinterpret_cast<const float4*>(
            qkv + (size_t)(t0 + n) * 768 + tensor * 256 + h * 32 + (hd4 << 2));
        float* dst = (tensor == 0 ? qs : (tensor == 1 ? ks : vs)) + n * QS + (hd4 << 2);
        *reinterpret_cast<float4*>(dst) = val;
    }
    if (tid < 64) {
        int wi = win & 63;
        int hh = ((wi >> 3) << 3) + (tid >> 3);
        int ww = ((wi & 7) << 3) + (tid & 7);
        int gh = (hh < 56) ? 0 : ((hh < 60) ? 1 : 2);
        int gw = (ww < 56) ? 0 : ((ww < 60) ? 1 : 2);
        grp[tid] = gh * 3 + gw;
    }
    __syncthreads();

    // l2-normalize q and k rows (128 threads, one row each)
    if (tid < 128) {
        float* base = (tid < 64 ? qs : ks) + (tid & 63) * QS;
        float4 r[8];
        float ss = 0.f;
#pragma unroll
        for (int d4 = 0; d4 < 8; ++d4) {
            r[d4] = *reinterpret_cast<const float4*>(base + (d4 << 2));
            ss += r[d4].x * r[d4].x + r[d4].y * r[d4].y
                + r[d4].z * r[d4].z + r[d4].w * r[d4].w;
        }
        float inv = 1.0f / fmaxf(sqrtf(ss), 1e-12f);
#pragma unroll
        for (int d4 = 0; d4 < 8; ++d4) {
            r[d4].x *= inv; r[d4].y *= inv; r[d4].z *= inv; r[d4].w *= inv;
            *reinterpret_cast<float4*>(base + (d4 << 2)) = r[d4];
        }
    }
    __syncthreads();

    const float scale = expf(fminf(logit_scale[h], 4.6051701859880914f));
    const int wi = win & 63;
    const bool edge = ((wi >> 3) == 7) || ((wi & 7) == 7);

    // ---- logits + softmax: 128 threads, 2 rows x 16 cols each
    if (tid < 128) {
        const int ip = tid >> 2;          // 0..31
        const int jq = tid & 3;           // 0..3
        const int i0 = ip << 1;
        const int i1 = i0 + 1;

        float4 qa[8], qb[8];
#pragma unroll
        for (int d4 = 0; d4 < 8; ++d4) {
            qa[d4] = *reinterpret_cast<const float4*>(qs + i0 * QS + (d4 << 2));
            qb[d4] = *reinterpret_cast<const float4*>(qs + i1 * QS + (d4 << 2));
        }
        const int gi0 = grp[i0];
        const int gi1 = grp[i1];
        const float* rpb0 = g_rpb + h * 4096 + i0 * 64;
        const float* rpb1 = g_rpb + h * 4096 + i1 * 64;

        float lt0[16], lt1[16];
#pragma unroll
        for (int jj = 0; jj < 16; ++jj) {
            const int j = (jj << 2) + jq;
            const float* kr = ks + j * QS;
            float d0 = 0.f, d1 = 0.f;
#pragma unroll
            for (int d4 = 0; d4 < 8; ++d4) {
                float4 k4 = *reinterpret_cast<const float4*>(kr + (d4 << 2));
                d0 = fmaf(qa[d4].x, k4.x, d0);
                d0 = fmaf(qa[d4].y, k4.y, d0);
                d0 = fmaf(qa[d4].z, k4.z, d0);
                d0 = fmaf(qa[d4].w, k4.w, d0);
                d1 = fmaf(qb[d4].x, k4.x, d1);
                d1 = fmaf(qb[d4].y, k4.y, d1);
                d1 = fmaf(qb[d4].z, k4.z, d1);
                d1 = fmaf(qb[d4].w, k4.w, d1);
            }
            float v0 = fmaf(scale, d0, rpb0[j]);
            float v1 = fmaf(scale, d1, rpb1[j]);
            if (edge) {
                int gj = grp[j];
                if (gi0 != gj) v0 -= 100.0f;
                if (gi1 != gj) v1 -= 100.0f;
            }
            lt0[jj] = v0;
            lt1[jj] = v1;
        }

        // softmax row i0 (quad shfl over jq)
        float m0 = lt0[0], m1 = lt1[0];
#pragma unroll
        for (int jj = 1; jj < 16; ++jj) {
            m0 = fmaxf(m0, lt0[jj]);
            m1 = fmaxf(m1, lt1[jj]);
        }
        m0 = fmaxf(m0, __shfl_xor_sync(0xffffffffu, m0, 1));
        m0 = fmaxf(m0, __shfl_xor_sync(0xffffffffu, m0, 2));
        m1 = fmaxf(m1, __shfl_xor_sync(0xffffffffu, m1, 1));
        m1 = fmaxf(m1, __shfl_xor_sync(0xffffffffu, m1, 2));
        float s0 = 0.f, s1 = 0.f;
#pragma unroll
        for (int jj = 0; jj < 16; ++jj) {
            lt0[jj] = __expf(lt0[jj] - m0); s0 += lt0[jj];
            lt1[jj] = __expf(lt1[jj] - m1); s1 += lt1[jj];
        }
        s0 += __shfl_xor_sync(0xffffffffu, s0, 1);
        s0 += __shfl_xor_sync(0xffffffffu, s0, 2);
        s1 += __shfl_xor_sync(0xffffffffu, s1, 1);
        s1 += __shfl_xor_sync(0xffffffffu, s1, 2);
        const float inv0 = 1.0f / s0;
        const float inv1 = 1.0f / s1;
#pragma unroll
        for (int jj = 0; jj < 16; ++jj) {
            ps[i0 * PS + (jj << 2) + jq] = lt0[jj] * inv0;
            ps[i1 * PS + (jj << 2) + jq] = lt1[jj] * inv1;
        }
    }
    __syncthreads();

    // ---- AV: 256 threads, 2 rows x 4 cols each
    {
        const int ip2 = tid >> 3;         // 0..31
        const int cg  = tid & 7;          // 0..7
        const int c0  = cg << 2;          // 0,4,...,28
        const int a0  = ip2 << 1;
        const int a1  = a0 + 1;
        const float* pr0 = ps + a0 * PS;
        const float* pr1 = ps + a1 * PS;

        float4 acc0 = make_float4(0.f, 0.f, 0.f, 0.f);
        float4 acc1 = make_float4(0.f, 0.f, 0.f, 0.f);
#pragma unroll
        for (int j4 = 0; j4 < 16; ++j4) {
            float4 p0 = *reinterpret_cast<const float4*>(pr0 + (j4 << 2));
            float4 p1 = *reinterpret_cast<const float4*>(pr1 + (j4 << 2));
            float a0j[4] = {p0.x, p0.y, p0.z, p0.w};
            float a1j[4] = {p1.x, p1.y, p1.z, p1.w};
#pragma unroll
            for (int e = 0; e < 4; ++e) {
                float4 v = *reinterpret_cast<const float4*>(
                    vs + ((j4 << 2) + e) * QS + c0);
                acc0.x = fmaf(a0j[e], v.x, acc0.x);
                acc0.y = fmaf(a0j[e], v.y, acc0.y);
                acc0.z = fmaf(a0j[e], v.z, acc0.z);
                acc0.w = fmaf(a0j[e], v.w, acc0.w);
                acc1.x = fmaf(a1j[e], v.x, acc1.x);
                acc1.y = fmaf(a1j[e], v.y, acc1.y);
                acc1.z = fmaf(a1j[e], v.z, acc1.z);
                acc1.w = fmaf(a1j[e], v.w, acc1.w);
            }
        }
        *reinterpret_cast<float4*>(out + (size_t)(t0 + a0) * 256 + h * 32 + c0) = acc0;
        *reinterpret_cast<float4*>(out + (size_t)(t0 + a1) * 256 + h * 32 + c0) = acc1;
    }
}

// ---------------------------------------------------------------------------
// out[row] = res[row] + LayerNorm(xin[row]) * g + b  — warp per row
// ---------------------------------------------------------------------------
__global__ __launch_bounds__(256)
void ln_add_kernel(const float* __restrict__ res, const float* __restrict__ xin,
                   const float* __restrict__ g, const float* __restrict__ b,
                   float* __restrict__ out) {
    const int row  = blockIdx.x * 8 + (threadIdx.x >> 5);
    const int lane = threadIdx.x & 31;
    const size_t base = (size_t)row * 256 + lane * 8;
    float4 v0 = *reinterpret_cast<const float4*>(xin + base);
    float4 v1 = *reinterpret_cast<const float4*>(xin + base + 4);
    float s = v0.x + v0.y + v0.z + v0.w + v1.x + v1.y + v1.z + v1.w;
#pragma unroll
    for (int o = 16; o > 0; o >>= 1) s += __shfl_xor_sync(0xffffffffu, s, o);
    float mean = s * (1.0f / 256.0f);
    float d0x = v0.x - mean, d0y = v0.y - mean, d0z = v0.z - mean, d0w = v0.w - mean;
    float d1x = v1.x - mean, d1y = v1.y - mean, d1z = v1.z - mean, d1w = v1.w - mean;
    float vv = d0x * d0x + d0y * d0y + d0z * d0z + d0w * d0w
             + d1x * d1x + d1y * d1y + d1z * d1z + d1w * d1w;
#pragma unroll
    for (int o = 16; o > 0; o >>= 1) vv += __shfl_xor_sync(0xffffffffu, vv, o);
    float rstd = rsqrtf(vv * (1.0f / 256.0f) + 1e-5f);
    float4 g0 = *reinterpret_cast<const float4*>(g + lane * 8);
    float4 g1 = *reinterpret_cast<const float4*>(g + lane * 8 + 4);
    float4 b0 = *reinterpret_cast<const float4*>(b + lane * 8);
    float4 b1 = *reinterpret_cast<const float4*>(b + lane * 8 + 4);
    float4 r0 = *reinterpret_cast<const float4*>(res + base);
    float4 r1 = *reinterpret_cast<const float4*>(res + base + 4);
    float4 o0, o1;
    o0.x = r0.x + d0x * rstd * g0.x + b0.x;
    o0.y = r0.y + d0y * rstd * g0.y + b0.y;
    o0.z = r0.z + d0z * rstd * g0.z + b0.z;
    o0.w = r0.w + d0w * rstd * g0.w + b0.w;
    o1.x = r1.x + d1x * rstd * g1.x + b1.x;
    o1.y = r1.y + d1y * rstd * g1.y + b1.y;
    o1.z = r1.z + d1z * rstd * g1.z + b1.z;
    o1.w = r1.w + d1w * rstd * g1.w + b1.w;
    *reinterpret_cast<float4*>(out + base)     = o0;
    *reinterpret_cast<float4*>(out + base + 4) = o1;
}

// ---------------------------------------------------------------------------
// launch
// ---------------------------------------------------------------------------
extern "C" void kernel_launch(void* const* d_in, const int* in_sizes, int n_in,
                              void* d_out, int out_size) {
    const float* x      = (const float*)d_in[0];
    const float* qkv_w  = (const float*)d_in[1];
    const float* q_bias = (const float*)d_in[2];
    const float* v_bias = (const float*)d_in[3];
    const float* lscale = (const float*)d_in[4];
    const float* cpb_w1 = (const float*)d_in[5];
    const float* cpb_b1 = (const float*)d_in[6];
    const float* cpb_w2 = (const float*)d_in[7];
    const float* proj_w = (const float*)d_in[8];
    const float* proj_b = (const float*)d_in[9];
    const float* n1g    = (const float*)d_in[10];
    const float* n1b    = (const float*)d_in[11];
    const float* n2g    = (const float*)d_in[12];
    const float* n2b    = (const float*)d_in[13];
    const float* fc1_w  = (const float*)d_in[14];
    const float* fc1_b  = (const float*)d_in[15];
    const float* fc2_w  = (const float*)d_in[16];
    const float* fc2_b  = (const float*)d_in[17];
    float* out = (float*)d_out;

    float *qkv, *attnout, *projimg, *x1, *hbuf, *mlp;
    cudaGetSymbolAddress((void**)&qkv,     g_qkv);
    cudaGetSymbolAddress((void**)&attnout, g_attnout);
    cudaGetSymbolAddress((void**)&projimg, g_projimg);
    cudaGetSymbolAddress((void**)&x1,      g_x1);
    cudaGetSymbolAddress((void**)&hbuf,    g_h);
    cudaGetSymbolAddress((void**)&mlp,     g_mlp);

    cpb_table_kernel<<<225, 256>>>(cpb_w1, cpb_b1, cpb_w2);
    rpb_kernel<<<(NH * NTOK * NTOK + 255) / 256, 256>>>();

    {   // QKV (gather shifted-window rows from x)
        dim3 grid(3 * CDIM / 128, MROWS / 128);
        tgemm_kernel<1, 0, 1, 0><<<grid, 256>>>(x, qkv_w, q_bias, v_bias, qkv,
                                                MROWS, 3 * CDIM, CDIM);
    }

    attn_kernel<<<(MROWS / NTOK) * NH, 256>>>(qkv, lscale, attnout);

    {   // proj (scatter rows back to image order)
        dim3 grid(CDIM / 128, MROWS / 128);
        tgemm_kernel<0, 1, 0, 0><<<grid, 256>>>(attnout, proj_w, proj_b, nullptr,
                                                projimg, MROWS, CDIM, CDIM);
    }

    ln_add_kernel<<<MROWS / 8, 256>>>(x, projimg, n1g, n1b, x1);

    {   // fc1 + exact GELU
        dim3 grid(HID / 128, MROWS / 128);
        tgemm_kernel<0, 0, 0, 1><<<grid, 256>>>(x1, fc1_w, fc1_b, nullptr, hbuf,
                                                MROWS, HID, CDIM);
    }

    {   // fc2
        dim3 grid(CDIM / 128, MROWS / 128);
        tgemm_kernel<0, 0, 0, 0><<<grid, 256>>>(hbuf, fc2_w, fc2_b, nullptr, mlp,
                                                MROWS, CDIM, HID);
    }

    ln_add_kernel<<<MROWS / 8, 256>>>(x1, mlp, n2g, n2b, out);
}

// round 16
// speedup vs baseline: 2.2713x; 1.0286x over previous
#include <cuda_runtime.h>
#include <math.h>
#include <stdint.h>

// ---------------------------------------------------------------------------
// Problem constants
// ---------------------------------------------------------------------------
#define BATCH   32
#define HRES    64
#define WRES    64
#define CDIM    256
#define WS      8
#define SHIFT   4
#define NH      8
#define NTOK    64
#define HD      32
#define HID     1024
#define CPB_HID 512
#define MROWS   (BATCH * HRES * WRES)   // 131072

// ---------------------------------------------------------------------------
// Scratch (allocation-free: __device__ globals)
// ---------------------------------------------------------------------------
__device__ float g_qkv[MROWS * 3 * CDIM];
__device__ float g_attnout[MROWS * CDIM];    // tf32-encoded (proj input only)
__device__ float g_projimg[MROWS * CDIM];
__device__ float g_x1[MROWS * CDIM];
__device__ float g_x1tf[MROWS * CDIM];       // tf32 copy of x1 (fc1 input)
__device__ float g_xtf[MROWS * CDIM];        // tf32 copy of x (qkv input)
__device__ float g_h[MROWS * HID];           // tf32-encoded (fc2 input only)
__device__ float g_mlp[MROWS * CDIM];
__device__ float g_wtf[786432];              // tf32 weights: qkv|proj|fc1|fc2
__device__ float g_bias_table[225 * NH];
__device__ float g_rpb[NH * NTOK * NTOK];

#define WOFF_QKV  0
#define WOFF_PROJ 196608
#define WOFF_FC1  262144
#define WOFF_FC2  524288

// ---------------------------------------------------------------------------
// shift+window permutation
// ---------------------------------------------------------------------------
__device__ __forceinline__ int permrow(int t) {
    int b   = t >> 12;
    int loc = t & 4095;
    int win = loc >> 6;
    int n   = loc & 63;
    int sh = ((win >> 3) << 3) + (n >> 3);
    int sw = ((win & 7) << 3) + (n & 7);
    int h = (sh + SHIFT) & 63;
    int w = (sw + SHIFT) & 63;
    return (b << 12) + (h << 6) + w;
}

__device__ __forceinline__ uint32_t f2tf32(float f) {
    uint32_t r;
    asm("cvt.rna.tf32.f32 %0, %1;" : "=r"(r) : "f"(f));
    return r;
}
__device__ __forceinline__ float f2tf32f(float f) { return __uint_as_float(f2tf32(f)); }

// ---------------------------------------------------------------------------
// tf32 pre-conversion pass (grid-stride float4)
// ---------------------------------------------------------------------------
__global__ __launch_bounds__(256)
void cvt_tf32_kernel(const float* __restrict__ src, float* __restrict__ dst, int n4) {
    int idx = blockIdx.x * 256 + threadIdx.x;
    int stride = gridDim.x * 256;
    for (; idx < n4; idx += stride) {
        float4 v = reinterpret_cast<const float4*>(src)[idx];
        v.x = f2tf32f(v.x); v.y = f2tf32f(v.y);
        v.z = f2tf32f(v.z); v.w = f2tf32f(v.w);
        reinterpret_cast<float4*>(dst)[idx] = v;
    }
}

// ---------------------------------------------------------------------------
// CPB table + rpb
// ---------------------------------------------------------------------------
__device__ __forceinline__ float cpb_feat(int v) {
    float tv = (float)v * (8.0f / 7.0f);
    float s  = (tv > 0.f) ? 1.f : ((tv < 0.f) ? -1.f : 0.f);
    return s * log2f(fabsf(tv) + 1.0f) * (1.0f / 3.0f);
}

__global__ __launch_bounds__(256)
void cpb_table_kernel(const float* __restrict__ w1, const float* __restrict__ b1,
                      const float* __restrict__ w2) {
    int p  = blockIdx.x;
    int iy = p / 15, ix = p % 15;
    float fy = cpb_feat(iy - 7);
    float fx = cpb_feat(ix - 7);
    int t = threadIdx.x;
    float acc[NH];
#pragma unroll
    for (int hh = 0; hh < NH; ++hh) acc[hh] = 0.f;
    for (int j = t; j < CPB_HID; j += 256) {
        float hmid = fy * w1[2 * j] + fx * w1[2 * j + 1] + b1[j];
        hmid = fmaxf(hmid, 0.f);
#pragma unroll
        for (int hh = 0; hh < NH; ++hh) acc[hh] += hmid * w2[hh * CPB_HID + j];
    }
    __shared__ float red[256];
    for (int hh = 0; hh < NH; ++hh) {
        red[t] = acc[hh];
        __syncthreads();
        for (int s = 128; s > 0; s >>= 1) {
            if (t < s) red[t] += red[t + s];
            __syncthreads();
        }
        if (t == 0) g_bias_table[p * NH + hh] = red[0];
        __syncthreads();
    }
}

__global__ __launch_bounds__(256)
void rpb_kernel() {
    int idx = blockIdx.x * 256 + threadIdx.x;
    if (idx >= NH * NTOK * NTOK) return;
    int h   = idx >> 12;
    int rem = idx & 4095;
    int i = rem >> 6, j = rem & 63;
    int ri = i >> 3, ci = i & 7, rj = j >> 3, cj = j & 7;
    int p = (ri - rj + 7) * 15 + (ci - cj + 7);
    float v = g_bias_table[p * NH + h];
    g_rpb[idx] = 16.0f / (1.0f + expf(-v));
}

// ---------------------------------------------------------------------------
// TF32 tensor-core GEMM, cp.async 3-stage pipeline.
// Inputs A and W are PRE-CONVERTED to tf32-encoded fp32 -> staging is a pure
// global->shared copy via LDGSTS (no registers, no cvt in the mainloop).
// 128x128 block, BK=16, 256 threads (8 warps 4(m) x 2(n)), warp 32x64.
// Fragment layout identical to the proven R14 configuration.
// ---------------------------------------------------------------------------
#define BKP 20
#define NSTG 3

__device__ __forceinline__ void mma_tf32(float* c, const uint32_t* a, const uint32_t* b) {
    asm volatile(
        "mma.sync.aligned.m16n8k8.row.col.f32.tf32.tf32.f32 "
        "{%0,%1,%2,%3}, {%4,%5,%6,%7}, {%8,%9}, {%0,%1,%2,%3};"
        : "+f"(c[0]), "+f"(c[1]), "+f"(c[2]), "+f"(c[3])
        : "r"(a[0]), "r"(a[1]), "r"(a[2]), "r"(a[3]), "r"(b[0]), "r"(b[1]));
}

__device__ __forceinline__ void cp_async16(uint32_t saddr, const float* gptr) {
    asm volatile("cp.async.ca.shared.global [%0], [%1], 16;\n"
                 :: "r"(saddr), "l"(gptr) : "memory");
}
__device__ __forceinline__ void cp_commit() {
    asm volatile("cp.async.commit_group;\n" ::: "memory");
}
__device__ __forceinline__ void cp_wait1() {
    asm volatile("cp.async.wait_group 1;\n" ::: "memory");
}

template <int RA, int RC, int BIASM, int ACT, int CVTO>
__global__ __launch_bounds__(256)
void tgemm_kernel(const float* __restrict__ A, const float* __restrict__ W,
                  const float* __restrict__ b0, const float* __restrict__ b1,
                  float* __restrict__ C, int M, int N, int K) {
    __shared__ float As[NSTG][128 * BKP];
    __shared__ float Ws[NSTG][128 * BKP];

    const int tid  = threadIdx.x;
    const int brow = blockIdx.y * 128;
    const int bcol = blockIdx.x * 128;

    const int lrow0 = tid >> 2;            // 0..63
    const int lrow1 = lrow0 + 64;
    const int lcol  = (tid & 3) << 2;      // 0,4,8,12
    int ar0 = brow + lrow0, ar1 = brow + lrow1;
    if (RA) { ar0 = permrow(ar0); ar1 = permrow(ar1); }
    const float* A0 = A + (size_t)ar0 * K + lcol;
    const float* A1 = A + (size_t)ar1 * K + lcol;
    const float* W0 = W + (size_t)(bcol + lrow0) * K + lcol;
    const float* W1 = W + (size_t)(bcol + lrow1) * K + lcol;

    const uint32_t sAbase = (uint32_t)__cvta_generic_to_shared(As)
                          + ((lrow0 * BKP + lcol) << 2);
    const uint32_t sWbase = (uint32_t)__cvta_generic_to_shared(Ws)
                          + ((lrow0 * BKP + lcol) << 2);
    const uint32_t rowoff = (64 * BKP) << 2;       // lrow1 - lrow0
    const uint32_t stgoff = (128 * BKP) << 2;      // one stage

    const int lane   = tid & 31;
    const int wid    = tid >> 5;
    const int warp_m = wid & 3;
    const int warp_n = wid >> 2;
    const int qr = lane >> 2;
    const int qc = lane & 3;
    const int aoff = (warp_m * 32 + qr) * BKP + qc;
    const int woff = (warp_n * 64 + qr) * BKP + qc;

    float acc[2][8][4];
#pragma unroll
    for (int mi = 0; mi < 2; ++mi)
#pragma unroll
        for (int ni = 0; ni < 8; ++ni)
#pragma unroll
            for (int e = 0; e < 4; ++e) acc[mi][ni][e] = 0.f;

    const int ktiles = K >> 4;

    // prologue: issue stages 0 and 1
#pragma unroll
    for (int p = 0; p < 2; ++p) {
        const int kt = p << 4;
        const uint32_t so = p * stgoff;
        cp_async16(sAbase + so,          A0 + kt);
        cp_async16(sAbase + so + rowoff, A1 + kt);
        cp_async16(sWbase + so,          W0 + kt);
        cp_async16(sWbase + so + rowoff, W1 + kt);
        cp_commit();
    }

    int buf = 0;
    for (int it = 0; it < ktiles; ++it) {
        cp_wait1();
        __syncthreads();

        // issue stage it+2 (into the buffer consumed at it-1; safe post-sync)
        const int nt = it + 2;
        if (nt < ktiles) {
            const int kt = nt << 4;
            const int nb = (buf + 2 >= NSTG) ? buf + 2 - NSTG : buf + 2;
            const uint32_t so = nb * stgoff;
            cp_async16(sAbase + so,          A0 + kt);
            cp_async16(sAbase + so + rowoff, A1 + kt);
            cp_async16(sWbase + so,          W0 + kt);
            cp_async16(sWbase + so + rowoff, W1 + kt);
        }
        cp_commit();

        const float* Asm = As[buf] + aoff;
        const float* Wsm = Ws[buf] + woff;
#pragma unroll
        for (int ks = 0; ks < 2; ++ks) {
            const int kk = ks * 8;
            uint32_t afr[2][4];
#pragma unroll
            for (int mi = 0; mi < 2; ++mi) {
                const float* p = Asm + mi * 16 * BKP + kk;
                afr[mi][0] = __float_as_uint(p[0]);
                afr[mi][1] = __float_as_uint(p[8 * BKP]);
                afr[mi][2] = __float_as_uint(p[4]);
                afr[mi][3] = __float_as_uint(p[8 * BKP + 4]);
            }
            uint32_t bfr[8][2];
#pragma unroll
            for (int ni = 0; ni < 8; ++ni) {
                const float* p = Wsm + ni * 8 * BKP + kk;
                bfr[ni][0] = __float_as_uint(p[0]);
                bfr[ni][1] = __float_as_uint(p[4]);
            }
#pragma unroll
            for (int mi = 0; mi < 2; ++mi)
#pragma unroll
                for (int ni = 0; ni < 8; ++ni)
                    mma_tf32(acc[mi][ni], afr[mi], bfr[ni]);
        }
        buf = (buf + 1 == NSTG) ? 0 : buf + 1;
    }

    // ---- epilogue
#pragma unroll
    for (int mi = 0; mi < 2; ++mi) {
        int r0 = brow + warp_m * 32 + mi * 16 + qr;
        int r1 = r0 + 8;
        int cr0 = RC ? permrow(r0) : r0;
        int cr1 = RC ? permrow(r1) : r1;
        float* C0 = C + (size_t)cr0 * N;
        float* C1 = C + (size_t)cr1 * N;
#pragma unroll
        for (int ni = 0; ni < 8; ++ni) {
            int col = bcol + warp_n * 64 + ni * 8 + qc * 2;
            float bv0, bv1;
            if (BIASM == 0) {
                bv0 = b0[col]; bv1 = b0[col + 1];
            } else {
                bv0 = (col < 256) ? b0[col] : ((col < 512) ? 0.f : b1[col - 512]);
                int c1i = col + 1;
                bv1 = (c1i < 256) ? b0[c1i] : ((c1i < 512) ? 0.f : b1[c1i - 512]);
            }
            float v00 = acc[mi][ni][0] + bv0;
            float v01 = acc[mi][ni][1] + bv1;
            float v10 = acc[mi][ni][2] + bv0;
            float v11 = acc[mi][ni][3] + bv1;
            if (ACT == 1) {
                v00 = 0.5f * v00 * (1.0f + erff(v00 * 0.70710678118654752f));
                v01 = 0.5f * v01 * (1.0f + erff(v01 * 0.70710678118654752f));
                v10 = 0.5f * v10 * (1.0f + erff(v10 * 0.70710678118654752f));
                v11 = 0.5f * v11 * (1.0f + erff(v11 * 0.70710678118654752f));
            }
            if (CVTO == 1) {
                v00 = f2tf32f(v00); v01 = f2tf32f(v01);
                v10 = f2tf32f(v10); v11 = f2tf32f(v11);
            }
            *reinterpret_cast<float2*>(C0 + col) = make_float2(v00, v01);
            *reinterpret_cast<float2*>(C1 + col) = make_float2(v10, v11);
        }
    }
}

// ---------------------------------------------------------------------------
// Fused window attention (R15 proven; epilogue now writes tf32-encoded out,
// since attnout is consumed only by the proj GEMM)
// ---------------------------------------------------------------------------
#define QS 36
#define PS 68

__global__ __launch_bounds__(256)
void attn_kernel(const float* __restrict__ qkv, const float* __restrict__ logit_scale,
                 float* __restrict__ out) {
    __shared__ float qs[NTOK * QS];
    __shared__ float ks[NTOK * QS];
    __shared__ float vs[NTOK * QS];
    __shared__ float ps[NTOK * PS];
    __shared__ int   grp[NTOK];

    const int blk = blockIdx.x;
    const int win = blk >> 3;
    const int h   = blk & 7;
    const int tid = threadIdx.x;
    const int t0  = win << 6;

    for (int e4 = tid; e4 < 1536; e4 += 256) {
        int tensor = e4 >> 9;
        int rem = e4 & 511;
        int n = rem >> 3;
        int hd4 = rem & 7;
        float4 val = *reinterpret_cast<const float4*>(
            qkv + (size_t)(t0 + n) * 768 + tensor * 256 + h * 32 + (hd4 << 2));
        float* dst = (tensor == 0 ? qs : (tensor == 1 ? ks : vs)) + n * QS + (hd4 << 2);
        *reinterpret_cast<float4*>(dst) = val;
    }
    if (tid < 64) {
        int wi = win & 63;
        int hh = ((wi >> 3) << 3) + (tid >> 3);
        int ww = ((wi & 7) << 3) + (tid & 7);
        int gh = (hh < 56) ? 0 : ((hh < 60) ? 1 : 2);
        int gw = (ww < 56) ? 0 : ((ww < 60) ? 1 : 2);
        grp[tid] = gh * 3 + gw;
    }
    __syncthreads();

    if (tid < 128) {
        float* base = (tid < 64 ? qs : ks) + (tid & 63) * QS;
        float4 r[8];
        float ss = 0.f;
#pragma unroll
        for (int d4 = 0; d4 < 8; ++d4) {
            r[d4] = *reinterpret_cast<const float4*>(base + (d4 << 2));
            ss += r[d4].x * r[d4].x + r[d4].y * r[d4].y
                + r[d4].z * r[d4].z + r[d4].w * r[d4].w;
        }
        float inv = 1.0f / fmaxf(sqrtf(ss), 1e-12f);
#pragma unroll
        for (int d4 = 0; d4 < 8; ++d4) {
            r[d4].x *= inv; r[d4].y *= inv; r[d4].z *= inv; r[d4].w *= inv;
            *reinterpret_cast<float4*>(base + (d4 << 2)) = r[d4];
        }
    }
    __syncthreads();

    const float scale = expf(fminf(logit_scale[h], 4.6051701859880914f));
    const int wi = win & 63;
    const bool edge = ((wi >> 3) == 7) || ((wi & 7) == 7);

    if (tid < 128) {
        const int ip = tid >> 2;
        const int jq = tid & 3;
        const int i0 = ip << 1;
        const int i1 = i0 + 1;

        float4 qa[8], qb[8];
#pragma unroll
        for (int d4 = 0; d4 < 8; ++d4) {
            qa[d4] = *reinterpret_cast<const float4*>(qs + i0 * QS + (d4 << 2));
            qb[d4] = *reinterpret_cast<const float4*>(qs + i1 * QS + (d4 << 2));
        }
        const int gi0 = grp[i0];
        const int gi1 = grp[i1];
        const float* rpb0 = g_rpb + h * 4096 + i0 * 64;
        const float* rpb1 = g_rpb + h * 4096 + i1 * 64;

        float lt0[16], lt1[16];
#pragma unroll
        for (int jj = 0; jj < 16; ++jj) {
            const int j = (jj << 2) + jq;
            const float* kr = ks + j * QS;
            float d0 = 0.f, d1 = 0.f;
#pragma unroll
            for (int d4 = 0; d4 < 8; ++d4) {
                float4 k4 = *reinterpret_cast<const float4*>(kr + (d4 << 2));
                d0 = fmaf(qa[d4].x, k4.x, d0);
                d0 = fmaf(qa[d4].y, k4.y, d0);
                d0 = fmaf(qa[d4].z, k4.z, d0);
                d0 = fmaf(qa[d4].w, k4.w, d0);
                d1 = fmaf(qb[d4].x, k4.x, d1);
                d1 = fmaf(qb[d4].y, k4.y, d1);
                d1 = fmaf(qb[d4].z, k4.z, d1);
                d1 = fmaf(qb[d4].w, k4.w, d1);
            }
            float v0 = fmaf(scale, d0, rpb0[j]);
            float v1 = fmaf(scale, d1, rpb1[j]);
            if (edge) {
                int gj = grp[j];
                if (gi0 != gj) v0 -= 100.0f;
                if (gi1 != gj) v1 -= 100.0f;
            }
            lt0[jj] = v0;
            lt1[jj] = v1;
        }

        float m0 = lt0[0], m1 = lt1[0];
#pragma unroll
        for (int jj = 1; jj < 16; ++jj) {
            m0 = fmaxf(m0, lt0[jj]);
            m1 = fmaxf(m1, lt1[jj]);
        }
        m0 = fmaxf(m0, __shfl_xor_sync(0xffffffffu, m0, 1));
        m0 = fmaxf(m0, __shfl_xor_sync(0xffffffffu, m0, 2));
        m1 = fmaxf(m1, __shfl_xor_sync(0xffffffffu, m1, 1));
        m1 = fmaxf(m1, __shfl_xor_sync(0xffffffffu, m1, 2));
        float s0 = 0.f, s1 = 0.f;
#pragma unroll
        for (int jj = 0; jj < 16; ++jj) {
            lt0[jj] = __expf(lt0[jj] - m0); s0 += lt0[jj];
            lt1[jj] = __expf(lt1[jj] - m1); s1 += lt1[jj];
        }
        s0 += __shfl_xor_sync(0xffffffffu, s0, 1);
        s0 += __shfl_xor_sync(0xffffffffu, s0, 2);
        s1 += __shfl_xor_sync(0xffffffffu, s1, 1);
        s1 += __shfl_xor_sync(0xffffffffu, s1, 2);
        const float inv0 = 1.0f / s0;
        const float inv1 = 1.0f / s1;
#pragma unroll
        for (int jj = 0; jj < 16; ++jj) {
            ps[i0 * PS + (jj << 2) + jq] = lt0[jj] * inv0;
            ps[i1 * PS + (jj << 2) + jq] = lt1[jj] * inv1;
        }
    }
    __syncthreads();

    {
        const int ip2 = tid >> 3;
        const int cg  = tid & 7;
        const int c0  = cg << 2;
        const int a0  = ip2 << 1;
        const int a1  = a0 + 1;
        const float* pr0 = ps + a0 * PS;
        const float* pr1 = ps + a1 * PS;

        float4 acc0 = make_float4(0.f, 0.f, 0.f, 0.f);
        float4 acc1 = make_float4(0.f, 0.f, 0.f, 0.f);
#pragma unroll
        for (int j4 = 0; j4 < 16; ++j4) {
            float4 p0 = *reinterpret_cast<const float4*>(pr0 + (j4 << 2));
            float4 p1 = *reinterpret_cast<const float4*>(pr1 + (j4 << 2));
            float a0j[4] = {p0.x, p0.y, p0.z, p0.w};
            float a1j[4] = {p1.x, p1.y, p1.z, p1.w};
#pragma unroll
            for (int e = 0; e < 4; ++e) {
                float4 v = *reinterpret_cast<const float4*>(
                    vs + ((j4 << 2) + e) * QS + c0);
                acc0.x = fmaf(a0j[e], v.x, acc0.x);
                acc0.y = fmaf(a0j[e], v.y, acc0.y);
                acc0.z = fmaf(a0j[e], v.z, acc0.z);
                acc0.w = fmaf(a0j[e], v.w, acc0.w);
                acc1.x = fmaf(a1j[e], v.x, acc1.x);
                acc1.y = fmaf(a1j[e], v.y, acc1.y);
                acc1.z = fmaf(a1j[e], v.z, acc1.z);
                acc1.w = fmaf(a1j[e], v.w, acc1.w);
            }
        }
        // tf32-encode (attnout feeds only the proj GEMM)
        acc0.x = f2tf32f(acc0.x); acc0.y = f2tf32f(acc0.y);
        acc0.z = f2tf32f(acc0.z); acc0.w = f2tf32f(acc0.w);
        acc1.x = f2tf32f(acc1.x); acc1.y = f2tf32f(acc1.y);
        acc1.z = f2tf32f(acc1.z); acc1.w = f2tf32f(acc1.w);
        *reinterpret_cast<float4*>(out + (size_t)(t0 + a0) * 256 + h * 32 + c0) = acc0;
        *reinterpret_cast<float4*>(out + (size_t)(t0 + a1) * 256 + h * 32 + c0) = acc1;
    }
}

// ---------------------------------------------------------------------------
// out[row] = res[row] + LayerNorm(xin[row]) * g + b  — warp per row.
// WTF: also write a tf32-encoded copy (for the following GEMM's A input).
// ---------------------------------------------------------------------------
template <int WTF>
__global__ __launch_bounds__(256)
void ln_add_kernel(const float* __restrict__ res, const float* __restrict__ xin,
                   const float* __restrict__ g, const float* __restrict__ b,
                   float* __restrict__ out, float* __restrict__ out_tf) {
    const int row  = blockIdx.x * 8 + (threadIdx.x >> 5);
    const int lane = threadIdx.x & 31;
    const size_t base = (size_t)row * 256 + lane * 8;
    float4 v0 = *reinterpret_cast<const float4*>(xin + base);
    float4 v1 = *reinterpret_cast<const float4*>(xin + base + 4);
    float s = v0.x + v0.y + v0.z + v0.w + v1.x + v1.y + v1.z + v1.w;
#pragma unroll
    for (int o = 16; o > 0; o >>= 1) s += __shfl_xor_sync(0xffffffffu, s, o);
    float mean = s * (1.0f / 256.0f);
    float d0x = v0.x - mean, d0y = v0.y - mean, d0z = v0.z - mean, d0w = v0.w - mean;
    float d1x = v1.x - mean, d1y = v1.y - mean, d1z = v1.z - mean, d1w = v1.w - mean;
    float vv = d0x * d0x + d0y * d0y + d0z * d0z + d0w * d0w
             + d1x * d1x + d1y * d1y + d1z * d1z + d1w * d1w;
#pragma unroll
    for (int o = 16; o > 0; o >>= 1) vv += __shfl_xor_sync(0xffffffffu, vv, o);
    float rstd = rsqrtf(vv * (1.0f / 256.0f) + 1e-5f);
    float4 g0 = *reinterpret_cast<const float4*>(g + lane * 8);
    float4 g1 = *reinterpret_cast<const float4*>(g + lane * 8 + 4);
    float4 b0 = *reinterpret_cast<const float4*>(b + lane * 8);
    float4 b1 = *reinterpret_cast<const float4*>(b + lane * 8 + 4);
    float4 r0 = *reinterpret_cast<const float4*>(res + base);
    float4 r1 = *reinterpret_cast<const float4*>(res + base + 4);
    float4 o0, o1;
    o0.x = r0.x + d0x * rstd * g0.x + b0.x;
    o0.y = r0.y + d0y * rstd * g0.y + b0.y;
    o0.z = r0.z + d0z * rstd * g0.z + b0.z;
    o0.w = r0.w + d0w * rstd * g0.w + b0.w;
    o1.x = r1.x + d1x * rstd * g1.x + b1.x;
    o1.y = r1.y + d1y * rstd * g1.y + b1.y;
    o1.z = r1.z + d1z * rstd * g1.z + b1.z;
    o1.w = r1.w + d1w * rstd * g1.w + b1.w;
    *reinterpret_cast<float4*>(out + base)     = o0;
    *reinterpret_cast<float4*>(out + base + 4) = o1;
    if (WTF) {
        float4 t0 = o0, t1 = o1;
        t0.x = f2tf32f(t0.x); t0.y = f2tf32f(t0.y);
        t0.z = f2tf32f(t0.z); t0.w = f2tf32f(t0.w);
        t1.x = f2tf32f(t1.x); t1.y = f2tf32f(t1.y);
        t1.z = f2tf32f(t1.z); t1.w = f2tf32f(t1.w);
        *reinterpret_cast<float4*>(out_tf + base)     = t0;
        *reinterpret_cast<float4*>(out_tf + base + 4) = t1;
    }
}

// ---------------------------------------------------------------------------
// launch
// ---------------------------------------------------------------------------
extern "C" void kernel_launch(void* const* d_in, const int* in_sizes, int n_in,
                              void* d_out, int out_size) {
    const float* x      = (const float*)d_in[0];
    const float* qkv_w  = (const float*)d_in[1];
    const float* q_bias = (const float*)d_in[2];
    const float* v_bias = (const float*)d_in[3];
    const float* lscale = (const float*)d_in[4];
    const float* cpb_w1 = (const float*)d_in[5];
    const float* cpb_b1 = (const float*)d_in[6];
    const float* cpb_w2 = (const float*)d_in[7];
    const float* proj_w = (const float*)d_in[8];
    const float* proj_b = (const float*)d_in[9];
    const float* n1g    = (const float*)d_in[10];
    const float* n1b    = (const float*)d_in[11];
    const float* n2g    = (const float*)d_in[12];
    const float* n2b    = (const float*)d_in[13];
    const float* fc1_w  = (const float*)d_in[14];
    const float* fc1_b  = (const float*)d_in[15];
    const float* fc2_w  = (const float*)d_in[16];
    const float* fc2_b  = (const float*)d_in[17];
    float* out = (float*)d_out;

    float *qkv, *attnout, *projimg, *x1, *x1tf, *xtf, *hbuf, *mlp, *wtf;
    cudaGetSymbolAddress((void**)&qkv,     g_qkv);
    cudaGetSymbolAddress((void**)&attnout, g_attnout);
    cudaGetSymbolAddress((void**)&projimg, g_projimg);
    cudaGetSymbolAddress((void**)&x1,      g_x1);
    cudaGetSymbolAddress((void**)&x1tf,    g_x1tf);
    cudaGetSymbolAddress((void**)&xtf,     g_xtf);
    cudaGetSymbolAddress((void**)&hbuf,    g_h);
    cudaGetSymbolAddress((void**)&mlp,     g_mlp);
    cudaGetSymbolAddress((void**)&wtf,     g_wtf);

    // tf32 pre-conversion: x and all weights
    cvt_tf32_kernel<<<4096, 256>>>(x, xtf, MROWS * CDIM / 4);
    cvt_tf32_kernel<<<192, 256>>>(qkv_w,  wtf + WOFF_QKV,  196608 / 4);
    cvt_tf32_kernel<<<64, 256>>>(proj_w,  wtf + WOFF_PROJ, 65536 / 4);
    cvt_tf32_kernel<<<256, 256>>>(fc1_w,  wtf + WOFF_FC1,  262144 / 4);
    cvt_tf32_kernel<<<256, 256>>>(fc2_w,  wtf + WOFF_FC2,  262144 / 4);

    cpb_table_kernel<<<225, 256>>>(cpb_w1, cpb_b1, cpb_w2);
    rpb_kernel<<<(NH * NTOK * NTOK + 255) / 256, 256>>>();

    {   // QKV (gather shifted-window rows from pre-converted x)
        dim3 grid(3 * CDIM / 128, MROWS / 128);
        tgemm_kernel<1, 0, 1, 0, 0><<<grid, 256>>>(xtf, wtf + WOFF_QKV,
                                                   q_bias, v_bias, qkv,
                                                   MROWS, 3 * CDIM, CDIM);
    }

    attn_kernel<<<(MROWS / NTOK) * NH, 256>>>(qkv, lscale, attnout);

    {   // proj (scatter rows back to image order)
        dim3 grid(CDIM / 128, MROWS / 128);
        tgemm_kernel<0, 1, 0, 0, 0><<<grid, 256>>>(attnout, wtf + WOFF_PROJ,
                                                   proj_b, nullptr, projimg,
                                                   MROWS, CDIM, CDIM);
    }

    ln_add_kernel<1><<<MROWS / 8, 256>>>(x, projimg, n1g, n1b, x1, x1tf);

    {   // fc1 + exact GELU, output tf32-encoded (feeds only fc2)
        dim3 grid(HID / 128, MROWS / 128);
        tgemm_kernel<0, 0, 0, 1, 1><<<grid, 256>>>(x1tf, wtf + WOFF_FC1,
                                                   fc1_b, nullptr, hbuf,
                                                   MROWS, HID, CDIM);
    }

    {   // fc2
        dim3 grid(CDIM / 128, MROWS / 128);
        tgemm_kernel<0, 0, 0, 0, 0><<<grid, 256>>>(hbuf, wtf + WOFF_FC2,
                                                   fc2_b, nullptr, mlp,
                                                   MROWS, CDIM, HID);
    }

    ln_add_kernel<0><<<MROWS / 8, 256>>>(x1, mlp, n2g, n2b, out, nullptr);
}